// round 8
// baseline (speedup 1.0000x reference)
#include <cuda_runtime.h>
#include <math.h>
#include <stdint.h>

// ---------------- constants ----------------
#define N_IMG    2
#define A_TOTAL  39375
#define PRE      2000
#define POST     300
#define SORT_N   65536

// output layout offsets (floats)
#define OFF_LOCS    0
#define OFF_SCORES  315000
#define OFF_ROIS    472500
#define OFF_RIDX    474900
#define OFF_ANCH    475500

// h (conv output, NHWC per level): lvl0 base 0, lvl1 base 5120000, lvl2 base 6400000
__device__ float               g_h[6720000];
__device__ float               g_fg[N_IMG * A_TOTAL];
__device__ float               g_roi[N_IMG * A_TOTAL * 4];
__device__ unsigned long long  g_keys[N_IMG * SORT_N];
__device__ unsigned long long  g_keys2[N_IMG * SORT_N];
__device__ float               g_boxes[N_IMG * PRE * 4];
__device__ int                 g_valid[N_IMG * PRE];
__device__ unsigned long long  g_mask[N_IMG * PRE * 32];

// ---------------- packed f32x2 helpers ----------------
#define FMA2(d, a, b) \
    asm("fma.rn.f32x2 %0, %1, %2, %0;" : "+l"(d) : "l"(a), "l"(b))
#define UNPACK2(lo, hi, v) \
    do { unsigned int _ulo, _uhi; \
         asm("mov.b64 {%0, %1}, %2;" : "=r"(_ulo), "=r"(_uhi) : "l"(v)); \
         lo = __uint_as_float(_ulo); hi = __uint_as_float(_uhi); } while (0)

// profiler alignment no-ops (make conv the 4th launch)
__global__ void nop_k() {}

// ---------------- conv 3x3 + bias + relu (all 3 levels, one launch) ----------------
// R4 operand scheme (duplicated inputs, native weight pairs — zero packs),
// at the measured-best occupancy: __launch_bounds__(128, 4) = 16 warps/SM.
// acc pairs over oc: acc2[yy][qp*4+r] = (acc[oc=ty*4+qp*2, r], acc[oc+1, r])
__global__ __launch_bounds__(128, 4)
void conv3x3_relu_all(const float* __restrict__ f0, const float* __restrict__ f1,
                      const float* __restrict__ f2, const float* __restrict__ w,
                      const float* __restrict__ bias) {
    __shared__ __align__(16) float2 s_in2[8 * 6 * 36];   // duplicated (v,v)
    __shared__ __align__(16) float  s_w[8 * 9 * 64];     // [(ic*9+k9)][oc]

    int b = blockIdx.x;
    const float* x;
    int hoff, H, W, bx, by, bz;
    if (b < 800) {
        x = f0; hoff = 0; H = 100; W = 100;
        bx = b & 3; by = (b >> 2) % 25; bz = b / 100;
    } else if (b < 1008) {
        int l = b - 800;
        x = f1; hoff = 5120000; H = 50; W = 50;
        bx = l & 1; by = (l >> 1) % 13; bz = l / 26;
    } else {
        int l = b - 1008;
        x = f2; hoff = 6400000; H = 25; W = 25;
        bx = 0; by = l % 7; bz = l / 7;
    }

    const int tid = threadIdx.x;
    const int tx  = tid & 7;     // px group: px = tx*4 + r
    const int ty  = tid >> 3;    // oc group: oc = ty*4 + {0..3}
    const int x0  = bx * 32;
    const int y0  = by * 4;
    const int n   = bz >> 2;
    const int oc0 = (bz & 3) * 64;

    unsigned long long acc2[4][8];
#pragma unroll
    for (int a = 0; a < 4; a++)
#pragma unroll
        for (int c = 0; c < 8; c++) acc2[a][c] = 0ull;

    const float* xn = x + (size_t)n * 256 * H * W;

    for (int ic0 = 0; ic0 < 256; ic0 += 8) {
        // weights: 64 oc x 8 ic x 9
        for (int f = tid; f < 1152; f += 128) {
            int oc = f / 18;
            int kq = f % 18;
            const float4 v = *reinterpret_cast<const float4*>(
                w + (size_t)(oc0 + oc) * 2304 + ic0 * 9 + kq * 4);
            int k = kq * 4;
            s_w[(k + 0) * 64 + oc] = v.x;
            s_w[(k + 1) * 64 + oc] = v.y;
            s_w[(k + 2) * 64 + oc] = v.z;
            s_w[(k + 3) * 64 + oc] = v.w;
        }
        // input duplicated: 8 ic x 6 rows x 34 cols (zero padded to 36)
        for (int i = tid; i < 8 * 6 * 36; i += 128) {
            int ic  = i / 216;
            int rem = i % 216;
            int ry  = rem / 36;
            int xx  = rem % 36;
            float v = 0.f;
            int gy = y0 + ry - 1;
            int gx = x0 + xx - 1;
            if (xx < 34 && gy >= 0 && gy < H && gx >= 0 && gx < W)
                v = xn[(size_t)(ic0 + ic) * H * W + gy * W + gx];
            s_in2[i] = make_float2(v, v);
        }
        __syncthreads();

        for (int ic = 0; ic < 8; ic++) {
#pragma unroll
            for (int ky = 0; ky < 3; ky++) {
                // weight pairs direct from smem: w2[kx][qp] = (w[oc], w[oc+1])
                unsigned long long w2[3][2];
#pragma unroll
                for (int kx = 0; kx < 3; kx++) {
#pragma unroll
                    for (int qp = 0; qp < 2; qp++)
                        w2[kx][qp] = *reinterpret_cast<const unsigned long long*>(
                            &s_w[(ic * 9 + ky * 3 + kx) * 64 + ty * 4 + qp * 2]);
                }
#pragma unroll
                for (int yy = 0; yy < 4; yy++) {
                    const float2* row = &s_in2[ic * 216 + (yy + ky) * 36 + tx * 4];
                    unsigned long long d[6];
#pragma unroll
                    for (int j = 0; j < 6; j++)
                        d[j] = *reinterpret_cast<const unsigned long long*>(&row[j]);
#pragma unroll
                    for (int kx = 0; kx < 3; kx++)
#pragma unroll
                        for (int qp = 0; qp < 2; qp++)
#pragma unroll
                            for (int r = 0; r < 4; r++)
                                FMA2(acc2[yy][qp * 4 + r], w2[kx][qp], d[r + kx]);
                }
            }
        }
        __syncthreads();
    }

    float bv[4];
#pragma unroll
    for (int q = 0; q < 4; q++) bv[q] = bias[oc0 + ty * 4 + q];

#pragma unroll
    for (int yy = 0; yy < 4; yy++) {
        int gy = y0 + yy;
        if (gy >= H) continue;
#pragma unroll
        for (int r = 0; r < 4; r++) {
            int gx = x0 + tx * 4 + r;
            if (gx >= W) continue;
            float a0, a1, a2, a3;
            UNPACK2(a0, a1, acc2[yy][0 * 4 + r]);
            UNPACK2(a2, a3, acc2[yy][1 * 4 + r]);
            float* dst = g_h + hoff + ((size_t)(n * H * W) + (size_t)gy * W + gx) * 256 + oc0 + ty * 4;
            float4 o;
            o.x = fmaxf(a0 + bv[0], 0.f);
            o.y = fmaxf(a1 + bv[1], 0.f);
            o.z = fmaxf(a2 + bv[2], 0.f);
            o.w = fmaxf(a3 + bv[3], 0.f);
            *reinterpret_cast<float4*>(dst) = o;
        }
    }
}

// ---------------- heads: 18x256 projections + softmax fg ----------------
__global__ __launch_bounds__(256)
void heads_kernel(const float* __restrict__ score_w, const float* __restrict__ score_b,
                  const float* __restrict__ loc_w, const float* __restrict__ loc_b,
                  float* __restrict__ out) {
    __shared__ float s_w[18 * 256];
    __shared__ float s_b[18];
    int tid = threadIdx.x;
    for (int i = tid; i < 6 * 256; i += 256)  s_w[i] = score_w[i];
    for (int i = tid; i < 12 * 256; i += 256) s_w[6 * 256 + i] = loc_w[i];
    if (tid < 6)       s_b[tid] = score_b[tid];
    else if (tid < 18) s_b[tid] = loc_b[tid - 6];
    __syncthreads();

    int warp = tid >> 5, lane = tid & 31;
    int P = blockIdx.x * 8 + warp;
    if (P >= 26250) return;
    int n = P / 13125;
    int p = P % 13125;
    int aoff, hbase, ploc;
    if (p < 10000)      { ploc = p;         aoff = 0;     hbase = n * 2560000 + ploc * 256; }
    else if (p < 12500) { ploc = p - 10000; aoff = 30000; hbase = 5120000 + n * 640000 + ploc * 256; }
    else                { ploc = p - 12500; aoff = 37500; hbase = 6400000 + n * 160000 + ploc * 256; }

    const float4* hp = reinterpret_cast<const float4*>(&g_h[hbase]);
    float4 v0 = hp[lane];
    float4 v1 = hp[lane + 32];
    float hv[8] = {v0.x, v0.y, v0.z, v0.w, v1.x, v1.y, v1.z, v1.w};

    float res[18];
#pragma unroll
    for (int o = 0; o < 18; o++) {
        const float* wr = &s_w[o * 256];
        float4 wa = *reinterpret_cast<const float4*>(&wr[lane * 4]);
        float4 wb = *reinterpret_cast<const float4*>(&wr[128 + lane * 4]);
        float s = hv[0] * wa.x + hv[1] * wa.y + hv[2] * wa.z + hv[3] * wa.w +
                  hv[4] * wb.x + hv[5] * wb.y + hv[6] * wb.z + hv[7] * wb.w;
#pragma unroll
        for (int off = 16; off; off >>= 1) s += __shfl_xor_sync(0xffffffffu, s, off);
        res[o] = s + s_b[o];
    }

    if (lane == 0) {
        int aid0 = aoff + ploc * 3;
#pragma unroll
        for (int a = 0; a < 3; a++) {
            int aid = aid0 + a;
            float s0 = res[a * 2 + 0], s1 = res[a * 2 + 1];
            out[OFF_SCORES + (size_t)(n * A_TOTAL + aid) * 2 + 0] = s0;
            out[OFF_SCORES + (size_t)(n * A_TOTAL + aid) * 2 + 1] = s1;
            g_fg[n * A_TOTAL + aid] = 1.f / (1.f + expf(s0 - s1));
#pragma unroll
            for (int c = 0; c < 4; c++)
                out[OFF_LOCS + (size_t)(n * A_TOTAL + aid) * 4 + c] = res[6 + a * 4 + c];
        }
    }
}

// ---------------- propose: loc2bbox + clip + valid + sort key ----------------
__device__ __forceinline__ unsigned int flip_f(float f) {
    unsigned int b = __float_as_uint(f);
    return (b & 0x80000000u) ? ~b : (b | 0x80000000u);
}

__global__ void propose_kernel(const float* __restrict__ anchors, const float* __restrict__ out) {
    int t = blockIdx.x * 256 + threadIdx.x;
    if (t >= N_IMG * SORT_N) return;
    int n = t / SORT_N, s = t % SORT_N;
    unsigned long long key = ~0ull;
    if (s < A_TOTAL) {
        float4 lc = *reinterpret_cast<const float4*>(out + OFF_LOCS + (size_t)(n * A_TOTAL + s) * 4);
        float4 an = *reinterpret_cast<const float4*>(anchors + (size_t)s * 4);
        float sh = an.z - an.x, sw = an.w - an.y;
        float cy = an.x + 0.5f * sh, cx = an.y + 0.5f * sw;
        float ncy = lc.x * sh + cy, ncx = lc.y * sw + cx;
        float nh = expf(lc.z) * sh, nw = expf(lc.w) * sw;
        float y1 = fminf(fmaxf(ncy - 0.5f * nh, 0.f), 800.f);
        float x1 = fminf(fmaxf(ncx - 0.5f * nw, 0.f), 800.f);
        float y2 = fminf(fmaxf(ncy + 0.5f * nh, 0.f), 800.f);
        float x2 = fminf(fmaxf(ncx + 0.5f * nw, 0.f), 800.f);
        float4 r = make_float4(y1, x1, y2, x2);
        *reinterpret_cast<float4*>(&g_roi[(size_t)(n * A_TOTAL + s) * 4]) = r;
        bool valid = ((y2 - y1) >= 16.f) && ((x2 - x1) >= 16.f);
        float sc = valid ? g_fg[n * A_TOTAL + s] : -INFINITY;
        unsigned int u = flip_f(sc);
        key = ((unsigned long long)(~u) << 32) | (unsigned int)s;
    }
    g_keys[t] = key;
}

// ---------------- local sort: each 2048-run ascending ----------------
__global__ __launch_bounds__(1024) void local_sort2048() {
    __shared__ unsigned long long sm[2048];
    int base = blockIdx.x * 2048;
    int tid = threadIdx.x;
    sm[tid] = g_keys[base + tid];
    sm[tid + 1024] = g_keys[base + tid + 1024];
    __syncthreads();
    for (int k = 2; k <= 2048; k <<= 1) {
        for (int j = k >> 1; j > 0; j >>= 1) {
            int i1 = ((tid / j) * 2 * j) + (tid % j);
            int i2 = i1 + j;
            bool dir = ((i1 & k) == 0);
            unsigned long long a = sm[i1], b = sm[i2];
            if (dir ? (a > b) : (a < b)) { sm[i1] = b; sm[i2] = a; }
            __syncthreads();
        }
    }
    g_keys[base + tid] = sm[tid];
    g_keys[base + tid + 1024] = sm[tid + 1024];
}

// ---------------- tournament merge-reduce: keep smallest 2048 of two runs ----------------
__global__ __launch_bounds__(1024) void merge_reduce(const unsigned long long* __restrict__ in,
                                                     unsigned long long* __restrict__ outb,
                                                     int runs_out_per_img) {
    __shared__ unsigned long long sm[2048];
    int img = blockIdx.x / runs_out_per_img;
    int r   = blockIdx.x % runs_out_per_img;
    const unsigned long long* A = in + (size_t)img * SORT_N + (size_t)(2 * r) * 2048;
    const unsigned long long* B = A + 2048;
    int tid = threadIdx.x;
    {
        unsigned long long a0 = A[tid],        b0 = B[2047 - tid];
        unsigned long long a1 = A[tid + 1024], b1 = B[1023 - tid];
        sm[tid]        = a0 < b0 ? a0 : b0;
        sm[tid + 1024] = a1 < b1 ? a1 : b1;
    }
    __syncthreads();
    for (int j = 1024; j > 0; j >>= 1) {
        int i1 = ((tid / j) * 2 * j) + (tid % j);
        int i2 = i1 + j;
        unsigned long long a = sm[i1], b = sm[i2];
        if (a > b) { sm[i1] = b; sm[i2] = a; }
        __syncthreads();
    }
    unsigned long long* O = outb + (size_t)img * SORT_N + (size_t)r * 2048;
    O[tid] = sm[tid];
    O[tid + 1024] = sm[tid + 1024];
}

// ---------------- gather top-2000 boxes (final run lives in g_keys2, run 0) ----------------
__global__ void gather_topk() {
    int t = blockIdx.x * 256 + threadIdx.x;
    if (t >= N_IMG * PRE) return;
    int n = t / PRE, r = t % PRE;
    unsigned long long key = g_keys2[(size_t)n * SORT_N + r];
    unsigned int hi = (unsigned int)(key >> 32);
    int valid = hi < 0xFF800000u;
    unsigned int idx = (unsigned int)key;
    float4 bx = make_float4(0.f, 0.f, 0.f, 0.f);
    if (idx < A_TOTAL)
        bx = *reinterpret_cast<const float4*>(&g_roi[(size_t)(n * A_TOTAL + idx) * 4]);
    *reinterpret_cast<float4*>(&g_boxes[(size_t)t * 4]) = bx;
    g_valid[t] = valid;
}

// ---------------- NMS suppression bitmask ----------------
__global__ void nms_mask() {
    int t = blockIdx.x * 256 + threadIdx.x;
    int n = blockIdx.y;
    if (t >= PRE * 32) return;
    int i = t >> 5, w = t & 31;
    const float4 bi = *reinterpret_cast<const float4*>(&g_boxes[(size_t)(n * PRE + i) * 4]);
    float area_i = (bi.z - bi.x) * (bi.w - bi.y);
    unsigned long long m = 0ull;
    int j0 = w * 64;
    for (int b = 0; b < 64; b++) {
        int j = j0 + b;
        if (j <= i || j >= PRE) continue;
        float4 bj = *reinterpret_cast<const float4*>(&g_boxes[(size_t)(n * PRE + j) * 4]);
        float ty = fmaxf(bi.x, bj.x), txx = fmaxf(bi.y, bj.y);
        float by = fminf(bi.z, bj.z), bxx = fminf(bi.w, bj.w);
        float hh = fmaxf(by - ty, 0.f), ww = fmaxf(bxx - txx, 0.f);
        float inter = hh * ww;
        float area_j = (bj.z - bj.x) * (bj.w - bj.y);
        float iou = inter / (area_i + area_j - inter + 1e-12f);
        if (iou > 0.7f) m |= (1ull << b);
    }
    g_mask[((size_t)n * PRE + i) * 32 + w] = m;
}

// ---------------- greedy NMS reduce (word-wise) + parallel emit ----------------
__global__ void nms_finalize(float* __restrict__ out) {
    int n = blockIdx.x;
    int tid = threadIdx.x;
    __shared__ unsigned long long alive_sh[32];
    __shared__ unsigned long long colm[64];
    __shared__ int base_sh[32];

    for (int i = tid; i < POST * 4; i += 256) out[OFF_ROIS + (size_t)n * POST * 4 + i] = 0.f;
    for (int i = tid; i < POST; i += 256)     out[OFF_RIDX + (size_t)n * POST + i] = (float)n;
    __syncthreads();

    if (tid < 32) {
        int lane = tid;
        unsigned long long sup = 0ull;
        for (int b = 0; b < 64; b++) {
            int i = lane * 64 + b;
            if (i >= PRE || !g_valid[n * PRE + i]) sup |= (1ull << b);
        }
        const unsigned long long* mrow = &g_mask[(size_t)n * PRE * 32];

        for (int w = 0; w < 32; w++) {
            int i0 = w * 64 + lane;
            int i1 = i0 + 32;
            colm[lane]      = (i0 < PRE) ? mrow[(size_t)i0 * 32 + w] : 0ull;
            colm[lane + 32] = (i1 < PRE) ? mrow[(size_t)i1 * 32 + w] : 0ull;
            __syncwarp();
            unsigned long long alivew = 0ull;
            if (lane == w) {
                unsigned long long supw = sup;
                for (int b = 0; b < 64; b++) {
                    if (!((supw >> b) & 1ull)) {
                        alivew |= (1ull << b);
                        supw |= colm[b];
                    }
                }
            }
            alivew = __shfl_sync(0xffffffffu, alivew, w);
            if (lane == w) alive_sh[w] = alivew;
            unsigned long long am = alivew, acc = 0ull;
            while (am) {
                int bb = __ffsll((long long)am) - 1;
                am &= am - 1;
                acc |= mrow[(size_t)(w * 64 + bb) * 32 + lane];
            }
            sup |= acc;
            __syncwarp();
        }

        int pc = __popcll(alive_sh[lane]);
        int xsum = pc;
        for (int off = 1; off < 32; off <<= 1) {
            int y = __shfl_up_sync(0xffffffffu, xsum, off);
            if (lane >= off) xsum += y;
        }
        base_sh[lane] = xsum - pc;
    }
    __syncthreads();

    for (int i = tid; i < PRE; i += 256) {
        int w = i >> 6, b = i & 63;
        unsigned long long aw = alive_sh[w];
        if ((aw >> b) & 1ull) {
            int rank = base_sh[w] + __popcll(aw & ((1ull << b) - 1ull));
            if (rank < POST) {
                float4 bx = *reinterpret_cast<const float4*>(&g_boxes[(size_t)(n * PRE + i) * 4]);
                float* dst = out + OFF_ROIS + (size_t)(n * POST + rank) * 4;
                dst[0] = bx.x; dst[1] = bx.y; dst[2] = bx.z; dst[3] = bx.w;
            }
        }
    }
}

// ---------------- launch ----------------
extern "C" void kernel_launch(void* const* d_in, const int* in_sizes, int n_in,
                              void* d_out, int out_size) {
    const float* feat0   = (const float*)d_in[0];
    const float* feat1   = (const float*)d_in[1];
    const float* feat2   = (const float*)d_in[2];
    const float* conv_w  = (const float*)d_in[3];
    const float* conv_b  = (const float*)d_in[4];
    const float* score_w = (const float*)d_in[5];
    const float* score_b = (const float*)d_in[6];
    const float* loc_w   = (const float*)d_in[7];
    const float* loc_b   = (const float*)d_in[8];
    const float* anchors = (const float*)d_in[9];
    float* out = (float*)d_out;

    unsigned long long *k1, *k2;
    cudaGetSymbolAddress((void**)&k1, g_keys);
    cudaGetSymbolAddress((void**)&k2, g_keys2);

    // 3 no-op launches so the conv is the 4th launch (= the one ncu captures)
    nop_k<<<1, 32>>>();
    nop_k<<<1, 32>>>();
    nop_k<<<1, 32>>>();

    conv3x3_relu_all<<<1064, 128>>>(feat0, feat1, feat2, conv_w, conv_b);
    heads_kernel<<<3282, 256>>>(score_w, score_b, loc_w, loc_b, out);
    propose_kernel<<<512, 256>>>(anchors, out);

    local_sort2048<<<64, 1024>>>();
    merge_reduce<<<32, 1024>>>(k1, k2, 16);
    merge_reduce<<<16, 1024>>>(k2, k1, 8);
    merge_reduce<<< 8, 1024>>>(k1, k2, 4);
    merge_reduce<<< 4, 1024>>>(k2, k1, 2);
    merge_reduce<<< 2, 1024>>>(k1, k2, 1);

    gather_topk<<<16, 256>>>();
    nms_mask<<<dim3(250, 2), 256>>>();
    nms_finalize<<<2, 256>>>(out);

    cudaMemcpyAsync(out + OFF_ANCH, anchors, (size_t)A_TOTAL * 4 * sizeof(float),
                    cudaMemcpyDeviceToDevice, 0);
}

// round 9
// speedup vs baseline: 2.6609x; 2.6609x over previous
#include <cuda_runtime.h>
#include <math.h>
#include <stdint.h>

// ---------------- constants ----------------
#define N_IMG    2
#define A_TOTAL  39375
#define PRE      2000
#define POST     300
#define SORT_N   65536

#define OFF_LOCS    0
#define OFF_SCORES  315000
#define OFF_ROIS    472500
#define OFF_RIDX    474900
#define OFF_ANCH    475500

// Winograd tiling: per image lvl0 50x50=2500, lvl1 25x25=625, lvl2 13x13=169 tiles
#define T_PER_IMG 3294
#define T_TOTAL   6588
#define T_PAD     6656      // 52 * 128

// h (conv output, NHWC per level): lvl0 base 0, lvl1 base 5120000, lvl2 base 6400000
__device__ float               g_h[6720000];
__device__ float               g_fg[N_IMG * A_TOTAL];
__device__ float               g_roi[N_IMG * A_TOTAL * 4];
__device__ unsigned long long  g_keys[N_IMG * SORT_N];
__device__ unsigned long long  g_keys2[N_IMG * SORT_N];
__device__ float               g_boxes[N_IMG * PRE * 4];
__device__ int                 g_valid[N_IMG * PRE];
__device__ unsigned long long  g_mask[N_IMG * PRE * 32];

// Winograd buffers (g_V zero-init; pad tiles never written -> stay zero)
__device__ float               g_U[16 * 256 * 256];              // [t][ic][oc]
__device__ float               g_V[16ull * T_PAD * 256];         // [t][tile][ic]
__device__ float               g_M[16ull * T_PAD * 256];         // [t][tile][oc]

// ---------------- packed f32x2 helpers ----------------
#define FMA2(d, a, b) \
    asm("fma.rn.f32x2 %0, %1, %2, %0;" : "+l"(d) : "l"(a), "l"(b))
#define UNPACK2(lo, hi, v) \
    do { unsigned int _ulo, _uhi; \
         asm("mov.b64 {%0, %1}, %2;" : "=r"(_ulo), "=r"(_uhi) : "l"(v)); \
         lo = __uint_as_float(_ulo); hi = __uint_as_float(_uhi); } while (0)

__global__ void nop_k() {}

// ---------------- Winograd weight transform: U = G g G^T ----------------
__global__ void wino_weights(const float* __restrict__ w) {
    int p = blockIdx.x * 256 + threadIdx.x;     // 65536 = ic x oc
    int oc = p & 255, ic = p >> 8;
    const float* gw = w + ((size_t)oc * 256 + ic) * 9;
    float g0 = gw[0], g1 = gw[1], g2 = gw[2];
    float g3 = gw[3], g4 = gw[4], g5 = gw[5];
    float g6 = gw[6], g7 = gw[7], g8 = gw[8];
    float T[4][3];
    T[0][0] = g0; T[0][1] = g1; T[0][2] = g2;
    T[1][0] = 0.5f * (g0 + g3 + g6); T[1][1] = 0.5f * (g1 + g4 + g7); T[1][2] = 0.5f * (g2 + g5 + g8);
    T[2][0] = 0.5f * (g0 - g3 + g6); T[2][1] = 0.5f * (g1 - g4 + g7); T[2][2] = 0.5f * (g2 - g5 + g8);
    T[3][0] = g6; T[3][1] = g7; T[3][2] = g8;
#pragma unroll
    for (int r = 0; r < 4; r++) {
        float u0 = T[r][0];
        float u1 = 0.5f * (T[r][0] + T[r][1] + T[r][2]);
        float u2 = 0.5f * (T[r][0] - T[r][1] + T[r][2]);
        float u3 = T[r][2];
        float* dst = g_U + (size_t)(r * 4) * 65536 + (size_t)ic * 256 + oc;
        dst[0]          = u0;
        dst[1ull*65536] = u1;
        dst[2ull*65536] = u2;
        dst[3ull*65536] = u3;
    }
}

// ---------------- Winograd input transform: V = B^T d B ----------------
// block: 32 ic x 32 tiles (one ty row strip); smem transpose from NCHW
__global__ __launch_bounds__(256) void wino_input(const float* __restrict__ f0,
                                                  const float* __restrict__ f1,
                                                  const float* __restrict__ f2) {
    __shared__ float s[32 * 265];    // [ic] pitch 265, rows 4 x cols 66
    int b = blockIdx.x, tid = threadIdx.x;
    const float* x;
    int H, W, TW, tbase, n, icg, ty, txg;
    if (b < 1600) {
        x = f0; H = 100; W = 100; TW = 50;
        n = b / 800; int r = b % 800; icg = r / 100; int r2 = r % 100;
        ty = r2 / 2; txg = r2 % 2; tbase = n * T_PER_IMG;
    } else if (b < 2000) {
        int l = b - 1600; x = f1; H = 50; W = 50; TW = 25;
        n = l / 200; int r = l % 200; icg = r / 25; ty = r % 25; txg = 0;
        tbase = n * T_PER_IMG + 2500;
    } else {
        int l = b - 2000; x = f2; H = 25; W = 25; TW = 13;
        n = l / 104; int r = l % 104; icg = r / 13; ty = r % 13; txg = 0;
        tbase = n * T_PER_IMG + 3125;
    }
    int tx0 = txg * 32;
    int HW = H * W;
    const float* xb = x + ((size_t)n * 256 + icg * 32) * HW;

    for (int f = tid; f < 32 * 264; f += 256) {
        int ic = f / 264, rem = f % 264, row = rem / 66, col = rem % 66;
        int gy = 2 * ty - 1 + row, gx = 2 * tx0 - 1 + col;
        float v = 0.f;
        if (gy >= 0 && gy < H && gx >= 0 && gx < W)
            v = xb[(size_t)ic * HW + gy * W + gx];
        s[ic * 265 + rem] = v;
    }
    __syncthreads();

    int ntile = TW - tx0; if (ntile > 32) ntile = 32;
#pragma unroll
    for (int it = 0; it < 4; it++) {
        int wk = it * 256 + tid;
        int ici = wk & 31, tl = wk >> 5;
        if (tl >= ntile) continue;
        const float* sp = s + ici * 265 + 2 * tl;
        float d[4][4];
#pragma unroll
        for (int i = 0; i < 4; i++)
#pragma unroll
            for (int j = 0; j < 4; j++) d[i][j] = sp[i * 66 + j];
        float e[4][4];
#pragma unroll
        for (int j = 0; j < 4; j++) {
            e[0][j] = d[0][j] - d[2][j];
            e[1][j] = d[1][j] + d[2][j];
            e[2][j] = d[2][j] - d[1][j];
            e[3][j] = d[1][j] - d[3][j];
        }
        size_t tile = (size_t)(tbase + ty * TW + tx0 + tl);
        float* dst = g_V + tile * 256 + icg * 32 + ici;
#pragma unroll
        for (int r = 0; r < 4; r++) {
            float v0 = e[r][0] - e[r][2];
            float v1 = e[r][1] + e[r][2];
            float v2 = e[r][2] - e[r][1];
            float v3 = e[r][1] - e[r][3];
            dst[(size_t)(r * 4 + 0) * T_PAD * 256] = v0;
            dst[(size_t)(r * 4 + 1) * T_PAD * 256] = v1;
            dst[(size_t)(r * 4 + 2) * T_PAD * 256] = v2;
            dst[(size_t)(r * 4 + 3) * T_PAD * 256] = v3;
        }
    }
}

// ---------------- Winograd GEMM: M_t = V_t (tiles x ic) * U_t (ic x oc) ----------------
// grid (52, 2, 16): CTA = 128 tiles x 128 oc, K=256 chunks of 16; FFMA2 pairs over oc.
__global__ __launch_bounds__(256, 2) void wino_gemm() {
    __shared__ float2 A2s[16 * 128];    // [k][tile] duplicated (v,v)
    __shared__ float  Bs[16 * 128];     // [k][oc]
    int t = threadIdx.x;
    int tz = blockIdx.z;
    int tile0 = blockIdx.x * 128;
    int oc0 = blockIdx.y * 128;
    const float* Vb = g_V + (size_t)tz * T_PAD * 256;
    const float* Ub = g_U + (size_t)tz * 65536;

    int arow = t >> 1, akq = (t & 1) * 8;
    int bidx0 = t * 2;
    int bk0 = bidx0 >> 5,        bo0 = (bidx0 & 31) * 4;
    int bk1 = (bidx0 + 1) >> 5,  bo1 = ((bidx0 + 1) & 31) * 4;

    unsigned long long acc2[8][4];
#pragma unroll
    for (int i = 0; i < 8; i++)
#pragma unroll
        for (int j = 0; j < 4; j++) acc2[i][j] = 0ull;

    int r0 = (t >> 4) * 8;
    int c0 = (t & 15) * 8;

    // preload chunk 0
    const float4* va = (const float4*)(Vb + (size_t)(tile0 + arow) * 256 + akq);
    float4 pa0 = va[0], pa1 = va[1];
    float4 pb0 = *(const float4*)(Ub + (size_t)bk0 * 256 + oc0 + bo0);
    float4 pb1 = *(const float4*)(Ub + (size_t)bk1 * 256 + oc0 + bo1);

    for (int k0 = 0; k0 < 256; k0 += 16) {
        // stage regs -> smem
#pragma unroll
        for (int i = 0; i < 4; i++)
            A2s[(akq + i) * 128 + arow] = make_float2(((float*)&pa0)[i], ((float*)&pa0)[i]);
#pragma unroll
        for (int i = 0; i < 4; i++)
            A2s[(akq + 4 + i) * 128 + arow] = make_float2(((float*)&pa1)[i], ((float*)&pa1)[i]);
        *(float4*)&Bs[bk0 * 128 + bo0] = pb0;
        *(float4*)&Bs[bk1 * 128 + bo1] = pb1;
        __syncthreads();

        // prefetch next chunk
        if (k0 + 16 < 256) {
            const float4* van = (const float4*)(Vb + (size_t)(tile0 + arow) * 256 + (k0 + 16) + akq);
            pa0 = van[0]; pa1 = van[1];
            pb0 = *(const float4*)(Ub + (size_t)(k0 + 16 + bk0) * 256 + oc0 + bo0);
            pb1 = *(const float4*)(Ub + (size_t)(k0 + 16 + bk1) * 256 + oc0 + bo1);
        }

        // compute chunk
#pragma unroll
        for (int k = 0; k < 16; k++) {
            unsigned long long a2[8], b2[4];
#pragma unroll
            for (int i = 0; i < 8; i++)
                a2[i] = *(const unsigned long long*)&A2s[k * 128 + r0 + i];
#pragma unroll
            for (int j = 0; j < 4; j++)
                b2[j] = *(const unsigned long long*)&Bs[k * 128 + c0 + 2 * j];
#pragma unroll
            for (int i = 0; i < 8; i++)
#pragma unroll
                for (int j = 0; j < 4; j++)
                    FMA2(acc2[i][j], a2[i], b2[j]);
        }
        __syncthreads();
    }

    // epilogue
#pragma unroll
    for (int i = 0; i < 8; i++) {
        float v[8];
#pragma unroll
        for (int j = 0; j < 4; j++) UNPACK2(v[2 * j], v[2 * j + 1], acc2[i][j]);
        float* dst = g_M + (size_t)tz * T_PAD * 256 + (size_t)(tile0 + r0 + i) * 256 + oc0 + c0;
        *(float4*)dst       = make_float4(v[0], v[1], v[2], v[3]);
        *(float4*)(dst + 4) = make_float4(v[4], v[5], v[6], v[7]);
    }
}

// ---------------- Winograd output transform: Y = A^T M A + bias, relu ----------------
__global__ __launch_bounds__(256) void wino_output(const float* __restrict__ bias) {
    int tile = blockIdx.x;          // 0..6587
    int oc = threadIdx.x;
    int n = tile / T_PER_IMG, r = tile % T_PER_IMG;
    int hoff, H, W, TW, lbase;
    if (r < 2500)      { hoff = 0;       H = 100; W = 100; TW = 50; lbase = 0; }
    else if (r < 3125) { hoff = 5120000; H = 50;  W = 50;  TW = 25; lbase = 2500; }
    else               { hoff = 6400000; H = 25;  W = 25;  TW = 13; lbase = 3125; }
    int lt = r - lbase, ty = lt / TW, tx = lt % TW;

    float m[16];
    const float* Mp = g_M + (size_t)tile * 256 + oc;
#pragma unroll
    for (int i = 0; i < 16; i++) m[i] = Mp[(size_t)i * T_PAD * 256];

    float e0[4], e1[4];
#pragma unroll
    for (int j = 0; j < 4; j++) {
        e0[j] = m[0 * 4 + j] + m[1 * 4 + j] + m[2 * 4 + j];
        e1[j] = m[1 * 4 + j] - m[2 * 4 + j] - m[3 * 4 + j];
    }
    float bv = bias[oc];
    float o00 = fmaxf(e0[0] + e0[1] + e0[2] + bv, 0.f);
    float o01 = fmaxf(e0[1] - e0[2] - e0[3] + bv, 0.f);
    float o10 = fmaxf(e1[0] + e1[1] + e1[2] + bv, 0.f);
    float o11 = fmaxf(e1[1] - e1[2] - e1[3] + bv, 0.f);

    int HW = H * W;
    int py = 2 * ty, px = 2 * tx;
    float* base = g_h + hoff + (size_t)n * HW * 256;
    if (py < H && px < W)         base[((size_t)(py * W + px)) * 256 + oc]           = o00;
    if (py < H && px + 1 < W)     base[((size_t)(py * W + px + 1)) * 256 + oc]       = o01;
    if (py + 1 < H && px < W)     base[((size_t)((py + 1) * W + px)) * 256 + oc]     = o10;
    if (py + 1 < H && px + 1 < W) base[((size_t)((py + 1) * W + px + 1)) * 256 + oc] = o11;
}

// ---------------- heads: 18x256 projections + softmax fg ----------------
__global__ __launch_bounds__(256)
void heads_kernel(const float* __restrict__ score_w, const float* __restrict__ score_b,
                  const float* __restrict__ loc_w, const float* __restrict__ loc_b,
                  float* __restrict__ out) {
    __shared__ float s_w[18 * 256];
    __shared__ float s_b[18];
    int tid = threadIdx.x;
    for (int i = tid; i < 6 * 256; i += 256)  s_w[i] = score_w[i];
    for (int i = tid; i < 12 * 256; i += 256) s_w[6 * 256 + i] = loc_w[i];
    if (tid < 6)       s_b[tid] = score_b[tid];
    else if (tid < 18) s_b[tid] = loc_b[tid - 6];
    __syncthreads();

    int warp = tid >> 5, lane = tid & 31;
    int P = blockIdx.x * 8 + warp;
    if (P >= 26250) return;
    int n = P / 13125;
    int p = P % 13125;
    int aoff, hbase, ploc;
    if (p < 10000)      { ploc = p;         aoff = 0;     hbase = n * 2560000 + ploc * 256; }
    else if (p < 12500) { ploc = p - 10000; aoff = 30000; hbase = 5120000 + n * 640000 + ploc * 256; }
    else                { ploc = p - 12500; aoff = 37500; hbase = 6400000 + n * 160000 + ploc * 256; }

    const float4* hp = reinterpret_cast<const float4*>(&g_h[hbase]);
    float4 v0 = hp[lane];
    float4 v1 = hp[lane + 32];
    float hv[8] = {v0.x, v0.y, v0.z, v0.w, v1.x, v1.y, v1.z, v1.w};

    float res[18];
#pragma unroll
    for (int o = 0; o < 18; o++) {
        const float* wr = &s_w[o * 256];
        float4 wa = *reinterpret_cast<const float4*>(&wr[lane * 4]);
        float4 wb = *reinterpret_cast<const float4*>(&wr[128 + lane * 4]);
        float s = hv[0] * wa.x + hv[1] * wa.y + hv[2] * wa.z + hv[3] * wa.w +
                  hv[4] * wb.x + hv[5] * wb.y + hv[6] * wb.z + hv[7] * wb.w;
#pragma unroll
        for (int off = 16; off; off >>= 1) s += __shfl_xor_sync(0xffffffffu, s, off);
        res[o] = s + s_b[o];
    }

    if (lane == 0) {
        int aid0 = aoff + ploc * 3;
#pragma unroll
        for (int a = 0; a < 3; a++) {
            int aid = aid0 + a;
            float s0 = res[a * 2 + 0], s1 = res[a * 2 + 1];
            out[OFF_SCORES + (size_t)(n * A_TOTAL + aid) * 2 + 0] = s0;
            out[OFF_SCORES + (size_t)(n * A_TOTAL + aid) * 2 + 1] = s1;
            g_fg[n * A_TOTAL + aid] = 1.f / (1.f + expf(s0 - s1));
#pragma unroll
            for (int c = 0; c < 4; c++)
                out[OFF_LOCS + (size_t)(n * A_TOTAL + aid) * 4 + c] = res[6 + a * 4 + c];
        }
    }
}

// ---------------- propose: loc2bbox + clip + valid + sort key ----------------
__device__ __forceinline__ unsigned int flip_f(float f) {
    unsigned int b = __float_as_uint(f);
    return (b & 0x80000000u) ? ~b : (b | 0x80000000u);
}

__global__ void propose_kernel(const float* __restrict__ anchors, const float* __restrict__ out) {
    int t = blockIdx.x * 256 + threadIdx.x;
    if (t >= N_IMG * SORT_N) return;
    int n = t / SORT_N, s = t % SORT_N;
    unsigned long long key = ~0ull;
    if (s < A_TOTAL) {
        float4 lc = *reinterpret_cast<const float4*>(out + OFF_LOCS + (size_t)(n * A_TOTAL + s) * 4);
        float4 an = *reinterpret_cast<const float4*>(anchors + (size_t)s * 4);
        float sh = an.z - an.x, sw = an.w - an.y;
        float cy = an.x + 0.5f * sh, cx = an.y + 0.5f * sw;
        float ncy = lc.x * sh + cy, ncx = lc.y * sw + cx;
        float nh = expf(lc.z) * sh, nw = expf(lc.w) * sw;
        float y1 = fminf(fmaxf(ncy - 0.5f * nh, 0.f), 800.f);
        float x1 = fminf(fmaxf(ncx - 0.5f * nw, 0.f), 800.f);
        float y2 = fminf(fmaxf(ncy + 0.5f * nh, 0.f), 800.f);
        float x2 = fminf(fmaxf(ncx + 0.5f * nw, 0.f), 800.f);
        float4 r = make_float4(y1, x1, y2, x2);
        *reinterpret_cast<float4*>(&g_roi[(size_t)(n * A_TOTAL + s) * 4]) = r;
        bool valid = ((y2 - y1) >= 16.f) && ((x2 - x1) >= 16.f);
        float sc = valid ? g_fg[n * A_TOTAL + s] : -INFINITY;
        unsigned int u = flip_f(sc);
        key = ((unsigned long long)(~u) << 32) | (unsigned int)s;
    }
    g_keys[t] = key;
}

// ---------------- local sort: each 2048-run ascending ----------------
__global__ __launch_bounds__(1024) void local_sort2048() {
    __shared__ unsigned long long sm[2048];
    int base = blockIdx.x * 2048;
    int tid = threadIdx.x;
    sm[tid] = g_keys[base + tid];
    sm[tid + 1024] = g_keys[base + tid + 1024];
    __syncthreads();
    for (int k = 2; k <= 2048; k <<= 1) {
        for (int j = k >> 1; j > 0; j >>= 1) {
            int i1 = ((tid / j) * 2 * j) + (tid % j);
            int i2 = i1 + j;
            bool dir = ((i1 & k) == 0);
            unsigned long long a = sm[i1], b = sm[i2];
            if (dir ? (a > b) : (a < b)) { sm[i1] = b; sm[i2] = a; }
            __syncthreads();
        }
    }
    g_keys[base + tid] = sm[tid];
    g_keys[base + tid + 1024] = sm[tid + 1024];
}

// ---------------- tournament merge-reduce ----------------
__global__ __launch_bounds__(1024) void merge_reduce(const unsigned long long* __restrict__ in,
                                                     unsigned long long* __restrict__ outb,
                                                     int runs_out_per_img) {
    __shared__ unsigned long long sm[2048];
    int img = blockIdx.x / runs_out_per_img;
    int r   = blockIdx.x % runs_out_per_img;
    const unsigned long long* A = in + (size_t)img * SORT_N + (size_t)(2 * r) * 2048;
    const unsigned long long* B = A + 2048;
    int tid = threadIdx.x;
    {
        unsigned long long a0 = A[tid],        b0 = B[2047 - tid];
        unsigned long long a1 = A[tid + 1024], b1 = B[1023 - tid];
        sm[tid]        = a0 < b0 ? a0 : b0;
        sm[tid + 1024] = a1 < b1 ? a1 : b1;
    }
    __syncthreads();
    for (int j = 1024; j > 0; j >>= 1) {
        int i1 = ((tid / j) * 2 * j) + (tid % j);
        int i2 = i1 + j;
        unsigned long long a = sm[i1], b = sm[i2];
        if (a > b) { sm[i1] = b; sm[i2] = a; }
        __syncthreads();
    }
    unsigned long long* O = outb + (size_t)img * SORT_N + (size_t)r * 2048;
    O[tid] = sm[tid];
    O[tid + 1024] = sm[tid + 1024];
}

// ---------------- gather top-2000 boxes ----------------
__global__ void gather_topk() {
    int t = blockIdx.x * 256 + threadIdx.x;
    if (t >= N_IMG * PRE) return;
    int n = t / PRE, r = t % PRE;
    unsigned long long key = g_keys2[(size_t)n * SORT_N + r];
    unsigned int hi = (unsigned int)(key >> 32);
    int valid = hi < 0xFF800000u;
    unsigned int idx = (unsigned int)key;
    float4 bx = make_float4(0.f, 0.f, 0.f, 0.f);
    if (idx < A_TOTAL)
        bx = *reinterpret_cast<const float4*>(&g_roi[(size_t)(n * A_TOTAL + idx) * 4]);
    *reinterpret_cast<float4*>(&g_boxes[(size_t)t * 4]) = bx;
    g_valid[t] = valid;
}

// ---------------- NMS suppression bitmask ----------------
__global__ void nms_mask() {
    int t = blockIdx.x * 256 + threadIdx.x;
    int n = blockIdx.y;
    if (t >= PRE * 32) return;
    int i = t >> 5, w = t & 31;
    const float4 bi = *reinterpret_cast<const float4*>(&g_boxes[(size_t)(n * PRE + i) * 4]);
    float area_i = (bi.z - bi.x) * (bi.w - bi.y);
    unsigned long long m = 0ull;
    int j0 = w * 64;
    for (int b = 0; b < 64; b++) {
        int j = j0 + b;
        if (j <= i || j >= PRE) continue;
        float4 bj = *reinterpret_cast<const float4*>(&g_boxes[(size_t)(n * PRE + j) * 4]);
        float ty = fmaxf(bi.x, bj.x), txx = fmaxf(bi.y, bj.y);
        float by = fminf(bi.z, bj.z), bxx = fminf(bi.w, bj.w);
        float hh = fmaxf(by - ty, 0.f), ww = fmaxf(bxx - txx, 0.f);
        float inter = hh * ww;
        float area_j = (bj.z - bj.x) * (bj.w - bj.y);
        float iou = inter / (area_i + area_j - inter + 1e-12f);
        if (iou > 0.7f) m |= (1ull << b);
    }
    g_mask[((size_t)n * PRE + i) * 32 + w] = m;
}

// ---------------- greedy NMS reduce (word-wise) + parallel emit ----------------
__global__ void nms_finalize(float* __restrict__ out) {
    int n = blockIdx.x;
    int tid = threadIdx.x;
    __shared__ unsigned long long alive_sh[32];
    __shared__ unsigned long long colm[64];
    __shared__ int base_sh[32];

    for (int i = tid; i < POST * 4; i += 256) out[OFF_ROIS + (size_t)n * POST * 4 + i] = 0.f;
    for (int i = tid; i < POST; i += 256)     out[OFF_RIDX + (size_t)n * POST + i] = (float)n;
    __syncthreads();

    if (tid < 32) {
        int lane = tid;
        unsigned long long sup = 0ull;
        for (int b = 0; b < 64; b++) {
            int i = lane * 64 + b;
            if (i >= PRE || !g_valid[n * PRE + i]) sup |= (1ull << b);
        }
        const unsigned long long* mrow = &g_mask[(size_t)n * PRE * 32];

        for (int w = 0; w < 32; w++) {
            int i0 = w * 64 + lane;
            int i1 = i0 + 32;
            colm[lane]      = (i0 < PRE) ? mrow[(size_t)i0 * 32 + w] : 0ull;
            colm[lane + 32] = (i1 < PRE) ? mrow[(size_t)i1 * 32 + w] : 0ull;
            __syncwarp();
            unsigned long long alivew = 0ull;
            if (lane == w) {
                unsigned long long supw = sup;
                for (int b = 0; b < 64; b++) {
                    if (!((supw >> b) & 1ull)) {
                        alivew |= (1ull << b);
                        supw |= colm[b];
                    }
                }
            }
            alivew = __shfl_sync(0xffffffffu, alivew, w);
            if (lane == w) alive_sh[w] = alivew;
            unsigned long long am = alivew, acc = 0ull;
            while (am) {
                int bb = __ffsll((long long)am) - 1;
                am &= am - 1;
                acc |= mrow[(size_t)(w * 64 + bb) * 32 + lane];
            }
            sup |= acc;
            __syncwarp();
        }

        int pc = __popcll(alive_sh[lane]);
        int xsum = pc;
        for (int off = 1; off < 32; off <<= 1) {
            int y = __shfl_up_sync(0xffffffffu, xsum, off);
            if (lane >= off) xsum += y;
        }
        base_sh[lane] = xsum - pc;
    }
    __syncthreads();

    for (int i = tid; i < PRE; i += 256) {
        int w = i >> 6, b = i & 63;
        unsigned long long aw = alive_sh[w];
        if ((aw >> b) & 1ull) {
            int rank = base_sh[w] + __popcll(aw & ((1ull << b) - 1ull));
            if (rank < POST) {
                float4 bx = *reinterpret_cast<const float4*>(&g_boxes[(size_t)(n * PRE + i) * 4]);
                float* dst = out + OFF_ROIS + (size_t)(n * POST + rank) * 4;
                dst[0] = bx.x; dst[1] = bx.y; dst[2] = bx.z; dst[3] = bx.w;
            }
        }
    }
}

// ---------------- launch ----------------
extern "C" void kernel_launch(void* const* d_in, const int* in_sizes, int n_in,
                              void* d_out, int out_size) {
    const float* feat0   = (const float*)d_in[0];
    const float* feat1   = (const float*)d_in[1];
    const float* feat2   = (const float*)d_in[2];
    const float* conv_w  = (const float*)d_in[3];
    const float* conv_b  = (const float*)d_in[4];
    const float* score_w = (const float*)d_in[5];
    const float* score_b = (const float*)d_in[6];
    const float* loc_w   = (const float*)d_in[7];
    const float* loc_b   = (const float*)d_in[8];
    const float* anchors = (const float*)d_in[9];
    float* out = (float*)d_out;

    unsigned long long *k1, *k2;
    cudaGetSymbolAddress((void**)&k1, g_keys);
    cudaGetSymbolAddress((void**)&k2, g_keys2);

    // Winograd conv pipeline (gemm is the 4th launch for ncu)
    wino_weights<<<256, 256>>>(conv_w);
    wino_input<<<2208, 256>>>(feat0, feat1, feat2);
    nop_k<<<1, 32>>>();
    wino_gemm<<<dim3(52, 2, 16), 256>>>();
    wino_output<<<T_TOTAL, 256>>>(conv_b);

    heads_kernel<<<3282, 256>>>(score_w, score_b, loc_w, loc_b, out);
    propose_kernel<<<512, 256>>>(anchors, out);

    local_sort2048<<<64, 1024>>>();
    merge_reduce<<<32, 1024>>>(k1, k2, 16);
    merge_reduce<<<16, 1024>>>(k2, k1, 8);
    merge_reduce<<< 8, 1024>>>(k1, k2, 4);
    merge_reduce<<< 4, 1024>>>(k2, k1, 2);
    merge_reduce<<< 2, 1024>>>(k1, k2, 1);

    gather_topk<<<16, 256>>>();
    nms_mask<<<dim3(250, 2), 256>>>();
    nms_finalize<<<2, 256>>>(out);

    cudaMemcpyAsync(out + OFF_ANCH, anchors, (size_t)A_TOTAL * 4 * sizeof(float),
                    cudaMemcpyDeviceToDevice, 0);
}

// round 12
// speedup vs baseline: 2.8368x; 1.0661x over previous
#include <cuda_runtime.h>
#include <math.h>
#include <stdint.h>

// ---------------- constants ----------------
#define N_IMG    2
#define A_TOTAL  39375
#define PRE      2000
#define POST     300
#define SORT_N   65536

#define OFF_LOCS    0
#define OFF_SCORES  315000
#define OFF_ROIS    472500
#define OFF_RIDX    474900
#define OFF_ANCH    475500

// Winograd tiling: per image lvl0 50x50=2500, lvl1 25x25=625, lvl2 13x13=169 tiles
#define T_PER_IMG 3294
#define T_TOTAL   6588
#define T_PAD     6656      // 52 * 128

// h (conv output, NHWC per level): lvl0 base 0, lvl1 base 5120000, lvl2 base 6400000
__device__ float               g_h[6720000];
__device__ float               g_fg[N_IMG * A_TOTAL];
__device__ float               g_roi[N_IMG * A_TOTAL * 4];
__device__ unsigned long long  g_keys[N_IMG * SORT_N];
__device__ unsigned long long  g_keys2[N_IMG * SORT_N];
__device__ float               g_boxes[N_IMG * PRE * 4];
__device__ int                 g_valid[N_IMG * PRE];
__device__ unsigned long long  g_mask[N_IMG * PRE * 32];

// Winograd buffers (g_V zero-init; pad tiles never written -> stay zero)
__device__ float               g_U[16 * 256 * 256];              // [t][ic][oc]
__device__ float               g_V[16ull * T_PAD * 256];         // [t][tile][ic]
__device__ float               g_M[16ull * T_PAD * 256];         // [t][tile][oc]

// ---------------- packed f32x2 helpers ----------------
#define FMA2(d, a, b) \
    asm("fma.rn.f32x2 %0, %1, %2, %0;" : "+l"(d) : "l"(a), "l"(b))
#define UNPACK2(lo, hi, v) \
    do { unsigned int _ulo, _uhi; \
         asm("mov.b64 {%0, %1}, %2;" : "=r"(_ulo), "=r"(_uhi) : "l"(v)); \
         lo = __uint_as_float(_ulo); hi = __uint_as_float(_uhi); } while (0)

__global__ void nop_k() {}

// ---------------- Winograd weight transform: U = G g G^T ----------------
__global__ void wino_weights(const float* __restrict__ w) {
    int p = blockIdx.x * 256 + threadIdx.x;     // 65536 = ic x oc
    int oc = p & 255, ic = p >> 8;
    const float* gw = w + ((size_t)oc * 256 + ic) * 9;
    float g0 = gw[0], g1 = gw[1], g2 = gw[2];
    float g3 = gw[3], g4 = gw[4], g5 = gw[5];
    float g6 = gw[6], g7 = gw[7], g8 = gw[8];
    float T[4][3];
    T[0][0] = g0; T[0][1] = g1; T[0][2] = g2;
    T[1][0] = 0.5f * (g0 + g3 + g6); T[1][1] = 0.5f * (g1 + g4 + g7); T[1][2] = 0.5f * (g2 + g5 + g8);
    T[2][0] = 0.5f * (g0 - g3 + g6); T[2][1] = 0.5f * (g1 - g4 + g7); T[2][2] = 0.5f * (g2 - g5 + g8);
    T[3][0] = g6; T[3][1] = g7; T[3][2] = g8;
#pragma unroll
    for (int r = 0; r < 4; r++) {
        float u0 = T[r][0];
        float u1 = 0.5f * (T[r][0] + T[r][1] + T[r][2]);
        float u2 = 0.5f * (T[r][0] - T[r][1] + T[r][2]);
        float u3 = T[r][2];
        float* dst = g_U + (size_t)(r * 4) * 65536 + (size_t)ic * 256 + oc;
        dst[0]          = u0;
        dst[1ull*65536] = u1;
        dst[2ull*65536] = u2;
        dst[3ull*65536] = u3;
    }
}

// ---------------- Winograd input transform: V = B^T d B ----------------
__global__ __launch_bounds__(256) void wino_input(const float* __restrict__ f0,
                                                  const float* __restrict__ f1,
                                                  const float* __restrict__ f2) {
    __shared__ float s[32 * 265];    // [ic] pitch 265, rows 4 x cols 66
    int b = blockIdx.x, tid = threadIdx.x;
    const float* x;
    int H, W, TW, tbase, n, icg, ty, txg;
    if (b < 1600) {
        x = f0; H = 100; W = 100; TW = 50;
        n = b / 800; int r = b % 800; icg = r / 100; int r2 = r % 100;
        ty = r2 / 2; txg = r2 % 2; tbase = n * T_PER_IMG;
    } else if (b < 2000) {
        int l = b - 1600; x = f1; H = 50; W = 50; TW = 25;
        n = l / 200; int r = l % 200; icg = r / 25; ty = r % 25; txg = 0;
        tbase = n * T_PER_IMG + 2500;
    } else {
        int l = b - 2000; x = f2; H = 25; W = 25; TW = 13;
        n = l / 104; int r = l % 104; icg = r / 13; ty = r % 13; txg = 0;
        tbase = n * T_PER_IMG + 3125;
    }
    int tx0 = txg * 32;
    int HW = H * W;
    const float* xb = x + ((size_t)n * 256 + icg * 32) * HW;

    for (int f = tid; f < 32 * 264; f += 256) {
        int ic = f / 264, rem = f % 264, row = rem / 66, col = rem % 66;
        int gy = 2 * ty - 1 + row, gx = 2 * tx0 - 1 + col;
        float v = 0.f;
        if (gy >= 0 && gy < H && gx >= 0 && gx < W)
            v = xb[(size_t)ic * HW + gy * W + gx];
        s[ic * 265 + rem] = v;
    }
    __syncthreads();

    int ntile = TW - tx0; if (ntile > 32) ntile = 32;
#pragma unroll
    for (int it = 0; it < 4; it++) {
        int wk = it * 256 + tid;
        int ici = wk & 31, tl = wk >> 5;
        if (tl >= ntile) continue;
        const float* sp = s + ici * 265 + 2 * tl;
        float d[4][4];
#pragma unroll
        for (int i = 0; i < 4; i++)
#pragma unroll
            for (int j = 0; j < 4; j++) d[i][j] = sp[i * 66 + j];
        float e[4][4];
#pragma unroll
        for (int j = 0; j < 4; j++) {
            e[0][j] = d[0][j] - d[2][j];
            e[1][j] = d[1][j] + d[2][j];
            e[2][j] = d[2][j] - d[1][j];
            e[3][j] = d[1][j] - d[3][j];
        }
        size_t tile = (size_t)(tbase + ty * TW + tx0 + tl);
        float* dst = g_V + tile * 256 + icg * 32 + ici;
#pragma unroll
        for (int r = 0; r < 4; r++) {
            float v0 = e[r][0] - e[r][2];
            float v1 = e[r][1] + e[r][2];
            float v2 = e[r][2] - e[r][1];
            float v3 = e[r][1] - e[r][3];
            dst[(size_t)(r * 4 + 0) * T_PAD * 256] = v0;
            dst[(size_t)(r * 4 + 1) * T_PAD * 256] = v1;
            dst[(size_t)(r * 4 + 2) * T_PAD * 256] = v2;
            dst[(size_t)(r * 4 + 3) * T_PAD * 256] = v3;
        }
    }
}

// ---------------- Winograd GEMM: M_t = V_t (tiles x ic) * U_t (ic x oc) ----------------
// grid (52, 2, 16): CTA = 128 tiles x 128 oc, K=256 chunks of 16; FFMA2 pairs over oc.
// B stored with float4-granular XOR swizzle q' = q ^ ((q>>3)&3) -> 2-phase (floor) loads.
// A loaded as broadcast LDS.128 (dup-pairs for 2 rows at once) -> 1 phase.
__global__ __launch_bounds__(256, 2) void wino_gemm() {
    __shared__ __align__(16) float2 A2s[16 * 128];    // [k][tile] duplicated (v,v)
    __shared__ __align__(16) float  Bs[16 * 128];     // [k][float4-slot q'] swizzled
    int t = threadIdx.x;
    int tz = blockIdx.z;
    int tile0 = blockIdx.x * 128;
    int oc0 = blockIdx.y * 128;
    const float* Vb = g_V + (size_t)tz * T_PAD * 256;
    const float* Ub = g_U + (size_t)tz * 65536;

    int arow = t >> 1, akq = (t & 1) * 8;
    int bidx0 = t * 2;
    int bk0 = bidx0 >> 5,       bq0 = bidx0 & 31;
    int bk1 = (bidx0 + 1) >> 5, bq1 = (bidx0 + 1) & 31;
    int bq0s = bq0 ^ ((bq0 >> 3) & 3);
    int bq1s = bq1 ^ ((bq1 >> 3) & 3);

    unsigned long long acc2[8][4];
#pragma unroll
    for (int i = 0; i < 8; i++)
#pragma unroll
        for (int j = 0; j < 4; j++) acc2[i][j] = 0ull;

    int r0 = (t >> 4) * 8;
    int qa0 = (t & 15) * 2, qa1 = qa0 + 1;
    int q0s = qa0 ^ ((qa0 >> 3) & 3);
    int q1s = qa1 ^ ((qa1 >> 3) & 3);

    // preload chunk 0
    const float4* va = (const float4*)(Vb + (size_t)(tile0 + arow) * 256 + akq);
    float4 pa0 = va[0], pa1 = va[1];
    float4 pb0 = *(const float4*)(Ub + (size_t)bk0 * 256 + oc0 + 4 * bq0);
    float4 pb1 = *(const float4*)(Ub + (size_t)bk1 * 256 + oc0 + 4 * bq1);

    for (int k0 = 0; k0 < 256; k0 += 16) {
        // stage regs -> smem
        A2s[(akq + 0) * 128 + arow] = make_float2(pa0.x, pa0.x);
        A2s[(akq + 1) * 128 + arow] = make_float2(pa0.y, pa0.y);
        A2s[(akq + 2) * 128 + arow] = make_float2(pa0.z, pa0.z);
        A2s[(akq + 3) * 128 + arow] = make_float2(pa0.w, pa0.w);
        A2s[(akq + 4) * 128 + arow] = make_float2(pa1.x, pa1.x);
        A2s[(akq + 5) * 128 + arow] = make_float2(pa1.y, pa1.y);
        A2s[(akq + 6) * 128 + arow] = make_float2(pa1.z, pa1.z);
        A2s[(akq + 7) * 128 + arow] = make_float2(pa1.w, pa1.w);
        *(float4*)&Bs[bk0 * 128 + 4 * bq0s] = pb0;
        *(float4*)&Bs[bk1 * 128 + 4 * bq1s] = pb1;
        __syncthreads();

        // prefetch next chunk
        if (k0 + 16 < 256) {
            const float4* van = (const float4*)(Vb + (size_t)(tile0 + arow) * 256 + (k0 + 16) + akq);
            pa0 = van[0]; pa1 = van[1];
            pb0 = *(const float4*)(Ub + (size_t)(k0 + 16 + bk0) * 256 + oc0 + 4 * bq0);
            pb1 = *(const float4*)(Ub + (size_t)(k0 + 16 + bk1) * 256 + oc0 + 4 * bq1);
        }

        // compute chunk
#pragma unroll
        for (int k = 0; k < 16; k++) {
            ulonglong2 aw0 = *(const ulonglong2*)&A2s[k * 128 + r0 + 0];
            ulonglong2 aw1 = *(const ulonglong2*)&A2s[k * 128 + r0 + 2];
            ulonglong2 aw2 = *(const ulonglong2*)&A2s[k * 128 + r0 + 4];
            ulonglong2 aw3 = *(const ulonglong2*)&A2s[k * 128 + r0 + 6];
            ulonglong2 bw0 = *(const ulonglong2*)&Bs[k * 128 + 4 * q0s];
            ulonglong2 bw1 = *(const ulonglong2*)&Bs[k * 128 + 4 * q1s];
            unsigned long long a2[8] = {aw0.x, aw0.y, aw1.x, aw1.y,
                                        aw2.x, aw2.y, aw3.x, aw3.y};
            unsigned long long b2[4] = {bw0.x, bw0.y, bw1.x, bw1.y};
#pragma unroll
            for (int i = 0; i < 8; i++)
#pragma unroll
                for (int j = 0; j < 4; j++)
                    FMA2(acc2[i][j], a2[i], b2[j]);
        }
        __syncthreads();
    }

    // epilogue
    int c0 = (t & 15) * 8;
#pragma unroll
    for (int i = 0; i < 8; i++) {
        float v[8];
#pragma unroll
        for (int j = 0; j < 4; j++) UNPACK2(v[2 * j], v[2 * j + 1], acc2[i][j]);
        float* dst = g_M + (size_t)tz * T_PAD * 256 + (size_t)(tile0 + r0 + i) * 256 + oc0 + c0;
        *(float4*)dst       = make_float4(v[0], v[1], v[2], v[3]);
        *(float4*)(dst + 4) = make_float4(v[4], v[5], v[6], v[7]);
    }
}

// ---------------- Winograd output transform: Y = A^T M A + bias, relu ----------------
__global__ __launch_bounds__(256) void wino_output(const float* __restrict__ bias) {
    int tile = blockIdx.x;          // 0..6587
    int oc = threadIdx.x;
    int n = tile / T_PER_IMG, r = tile % T_PER_IMG;
    int hoff, H, W, TW, lbase;
    if (r < 2500)      { hoff = 0;       H = 100; W = 100; TW = 50; lbase = 0; }
    else if (r < 3125) { hoff = 5120000; H = 50;  W = 50;  TW = 25; lbase = 2500; }
    else               { hoff = 6400000; H = 25;  W = 25;  TW = 13; lbase = 3125; }
    int lt = r - lbase, ty = lt / TW, tx = lt % TW;

    float m[16];
    const float* Mp = g_M + (size_t)tile * 256 + oc;
#pragma unroll
    for (int i = 0; i < 16; i++) m[i] = Mp[(size_t)i * T_PAD * 256];

    float e0[4], e1[4];
#pragma unroll
    for (int j = 0; j < 4; j++) {
        e0[j] = m[0 * 4 + j] + m[1 * 4 + j] + m[2 * 4 + j];
        e1[j] = m[1 * 4 + j] - m[2 * 4 + j] - m[3 * 4 + j];
    }
    float bv = bias[oc];
    float o00 = fmaxf(e0[0] + e0[1] + e0[2] + bv, 0.f);
    float o01 = fmaxf(e0[1] - e0[2] - e0[3] + bv, 0.f);
    float o10 = fmaxf(e1[0] + e1[1] + e1[2] + bv, 0.f);
    float o11 = fmaxf(e1[1] - e1[2] - e1[3] + bv, 0.f);

    int HW = H * W;
    int py = 2 * ty, px = 2 * tx;
    float* base = g_h + hoff + (size_t)n * HW * 256;
    if (py < H && px < W)         base[((size_t)(py * W + px)) * 256 + oc]           = o00;
    if (py < H && px + 1 < W)     base[((size_t)(py * W + px + 1)) * 256 + oc]       = o01;
    if (py + 1 < H && px < W)     base[((size_t)((py + 1) * W + px)) * 256 + oc]     = o10;
    if (py + 1 < H && px + 1 < W) base[((size_t)((py + 1) * W + px + 1)) * 256 + oc] = o11;
}

// ---------------- heads: 18x256 projections + softmax fg ----------------
__global__ __launch_bounds__(256)
void heads_kernel(const float* __restrict__ score_w, const float* __restrict__ score_b,
                  const float* __restrict__ loc_w, const float* __restrict__ loc_b,
                  float* __restrict__ out) {
    __shared__ float s_w[18 * 256];
    __shared__ float s_b[18];
    int tid = threadIdx.x;
    for (int i = tid; i < 6 * 256; i += 256)  s_w[i] = score_w[i];
    for (int i = tid; i < 12 * 256; i += 256) s_w[6 * 256 + i] = loc_w[i];
    if (tid < 6)       s_b[tid] = score_b[tid];
    else if (tid < 18) s_b[tid] = loc_b[tid - 6];
    __syncthreads();

    int warp = tid >> 5, lane = tid & 31;
    int P = blockIdx.x * 8 + warp;
    if (P >= 26250) return;
    int n = P / 13125;
    int p = P % 13125;
    int aoff, hbase, ploc;
    if (p < 10000)      { ploc = p;         aoff = 0;     hbase = n * 2560000 + ploc * 256; }
    else if (p < 12500) { ploc = p - 10000; aoff = 30000; hbase = 5120000 + n * 640000 + ploc * 256; }
    else                { ploc = p - 12500; aoff = 37500; hbase = 6400000 + n * 160000 + ploc * 256; }

    const float4* hp = reinterpret_cast<const float4*>(&g_h[hbase]);
    float4 v0 = hp[lane];
    float4 v1 = hp[lane + 32];
    float hv[8] = {v0.x, v0.y, v0.z, v0.w, v1.x, v1.y, v1.z, v1.w};

    float res[18];
#pragma unroll
    for (int o = 0; o < 18; o++) {
        const float* wr = &s_w[o * 256];
        float4 wa = *reinterpret_cast<const float4*>(&wr[lane * 4]);
        float4 wb = *reinterpret_cast<const float4*>(&wr[128 + lane * 4]);
        float s = hv[0] * wa.x + hv[1] * wa.y + hv[2] * wa.z + hv[3] * wa.w +
                  hv[4] * wb.x + hv[5] * wb.y + hv[6] * wb.z + hv[7] * wb.w;
#pragma unroll
        for (int off = 16; off; off >>= 1) s += __shfl_xor_sync(0xffffffffu, s, off);
        res[o] = s + s_b[o];
    }

    if (lane == 0) {
        int aid0 = aoff + ploc * 3;
#pragma unroll
        for (int a = 0; a < 3; a++) {
            int aid = aid0 + a;
            float s0 = res[a * 2 + 0], s1 = res[a * 2 + 1];
            out[OFF_SCORES + (size_t)(n * A_TOTAL + aid) * 2 + 0] = s0;
            out[OFF_SCORES + (size_t)(n * A_TOTAL + aid) * 2 + 1] = s1;
            g_fg[n * A_TOTAL + aid] = 1.f / (1.f + expf(s0 - s1));
#pragma unroll
            for (int c = 0; c < 4; c++)
                out[OFF_LOCS + (size_t)(n * A_TOTAL + aid) * 4 + c] = res[6 + a * 4 + c];
        }
    }
}

// ---------------- propose: loc2bbox + clip + valid + sort key ----------------
__device__ __forceinline__ unsigned int flip_f(float f) {
    unsigned int b = __float_as_uint(f);
    return (b & 0x80000000u) ? ~b : (b | 0x80000000u);
}

__global__ void propose_kernel(const float* __restrict__ anchors, const float* __restrict__ out) {
    int t = blockIdx.x * 256 + threadIdx.x;
    if (t >= N_IMG * SORT_N) return;
    int n = t / SORT_N, s = t % SORT_N;
    unsigned long long key = ~0ull;
    if (s < A_TOTAL) {
        float4 lc = *reinterpret_cast<const float4*>(out + OFF_LOCS + (size_t)(n * A_TOTAL + s) * 4);
        float4 an = *reinterpret_cast<const float4*>(anchors + (size_t)s * 4);
        float sh = an.z - an.x, sw = an.w - an.y;
        float cy = an.x + 0.5f * sh, cx = an.y + 0.5f * sw;
        float ncy = lc.x * sh + cy, ncx = lc.y * sw + cx;
        float nh = expf(lc.z) * sh, nw = expf(lc.w) * sw;
        float y1 = fminf(fmaxf(ncy - 0.5f * nh, 0.f), 800.f);
        float x1 = fminf(fmaxf(ncx - 0.5f * nw, 0.f), 800.f);
        float y2 = fminf(fmaxf(ncy + 0.5f * nh, 0.f), 800.f);
        float x2 = fminf(fmaxf(ncx + 0.5f * nw, 0.f), 800.f);
        float4 r = make_float4(y1, x1, y2, x2);
        *reinterpret_cast<float4*>(&g_roi[(size_t)(n * A_TOTAL + s) * 4]) = r;
        bool valid = ((y2 - y1) >= 16.f) && ((x2 - x1) >= 16.f);
        float sc = valid ? g_fg[n * A_TOTAL + s] : -INFINITY;
        unsigned int u = flip_f(sc);
        key = ((unsigned long long)(~u) << 32) | (unsigned int)s;
    }
    g_keys[t] = key;
}

// ---------------- local sort: each 2048-run ascending ----------------
__global__ __launch_bounds__(1024) void local_sort2048() {
    __shared__ unsigned long long sm[2048];
    int base = blockIdx.x * 2048;
    int tid = threadIdx.x;
    sm[tid] = g_keys[base + tid];
    sm[tid + 1024] = g_keys[base + tid + 1024];
    __syncthreads();
    for (int k = 2; k <= 2048; k <<= 1) {
        for (int j = k >> 1; j > 0; j >>= 1) {
            int i1 = ((tid / j) * 2 * j) + (tid % j);
            int i2 = i1 + j;
            bool dir = ((i1 & k) == 0);
            unsigned long long a = sm[i1], b = sm[i2];
            if (dir ? (a > b) : (a < b)) { sm[i1] = b; sm[i2] = a; }
            __syncthreads();
        }
    }
    g_keys[base + tid] = sm[tid];
    g_keys[base + tid + 1024] = sm[tid + 1024];
}

// ---------------- tournament merge-reduce ----------------
__global__ __launch_bounds__(1024) void merge_reduce(const unsigned long long* __restrict__ in,
                                                     unsigned long long* __restrict__ outb,
                                                     int runs_out_per_img) {
    __shared__ unsigned long long sm[2048];
    int img = blockIdx.x / runs_out_per_img;
    int r   = blockIdx.x % runs_out_per_img;
    const unsigned long long* A = in + (size_t)img * SORT_N + (size_t)(2 * r) * 2048;
    const unsigned long long* B = A + 2048;
    int tid = threadIdx.x;
    {
        unsigned long long a0 = A[tid],        b0 = B[2047 - tid];
        unsigned long long a1 = A[tid + 1024], b1 = B[1023 - tid];
        sm[tid]        = a0 < b0 ? a0 : b0;
        sm[tid + 1024] = a1 < b1 ? a1 : b1;
    }
    __syncthreads();
    for (int j = 1024; j > 0; j >>= 1) {
        int i1 = ((tid / j) * 2 * j) + (tid % j);
        int i2 = i1 + j;
        unsigned long long a = sm[i1], b = sm[i2];
        if (a > b) { sm[i1] = b; sm[i2] = a; }
        __syncthreads();
    }
    unsigned long long* O = outb + (size_t)img * SORT_N + (size_t)r * 2048;
    O[tid] = sm[tid];
    O[tid + 1024] = sm[tid + 1024];
}

// ---------------- gather top-2000 boxes ----------------
__global__ void gather_topk() {
    int t = blockIdx.x * 256 + threadIdx.x;
    if (t >= N_IMG * PRE) return;
    int n = t / PRE, r = t % PRE;
    unsigned long long key = g_keys2[(size_t)n * SORT_N + r];
    unsigned int hi = (unsigned int)(key >> 32);
    int valid = hi < 0xFF800000u;
    unsigned int idx = (unsigned int)key;
    float4 bx = make_float4(0.f, 0.f, 0.f, 0.f);
    if (idx < A_TOTAL)
        bx = *reinterpret_cast<const float4*>(&g_roi[(size_t)(n * A_TOTAL + idx) * 4]);
    *reinterpret_cast<float4*>(&g_boxes[(size_t)t * 4]) = bx;
    g_valid[t] = valid;
}

// ---------------- NMS suppression bitmask ----------------
__global__ void nms_mask() {
    int t = blockIdx.x * 256 + threadIdx.x;
    int n = blockIdx.y;
    if (t >= PRE * 32) return;
    int i = t >> 5, w = t & 31;
    const float4 bi = *reinterpret_cast<const float4*>(&g_boxes[(size_t)(n * PRE + i) * 4]);
    float area_i = (bi.z - bi.x) * (bi.w - bi.y);
    unsigned long long m = 0ull;
    int j0 = w * 64;
    for (int b = 0; b < 64; b++) {
        int j = j0 + b;
        if (j <= i || j >= PRE) continue;
        float4 bj = *reinterpret_cast<const float4*>(&g_boxes[(size_t)(n * PRE + j) * 4]);
        float ty = fmaxf(bi.x, bj.x), txx = fmaxf(bi.y, bj.y);
        float by = fminf(bi.z, bj.z), bxx = fminf(bi.w, bj.w);
        float hh = fmaxf(by - ty, 0.f), ww = fmaxf(bxx - txx, 0.f);
        float inter = hh * ww;
        float area_j = (bj.z - bj.x) * (bj.w - bj.y);
        float iou = inter / (area_i + area_j - inter + 1e-12f);
        if (iou > 0.7f) m |= (1ull << b);
    }
    g_mask[((size_t)n * PRE + i) * 32 + w] = m;
}

// ---------------- greedy NMS reduce (word-wise) + parallel emit ----------------
__global__ void nms_finalize(float* __restrict__ out) {
    int n = blockIdx.x;
    int tid = threadIdx.x;
    __shared__ unsigned long long alive_sh[32];
    __shared__ unsigned long long colm[64];
    __shared__ int base_sh[32];

    for (int i = tid; i < POST * 4; i += 256) out[OFF_ROIS + (size_t)n * POST * 4 + i] = 0.f;
    for (int i = tid; i < POST; i += 256)     out[OFF_RIDX + (size_t)n * POST + i] = (float)n;
    __syncthreads();

    if (tid < 32) {
        int lane = tid;
        unsigned long long sup = 0ull;
        for (int b = 0; b < 64; b++) {
            int i = lane * 64 + b;
            if (i >= PRE || !g_valid[n * PRE + i]) sup |= (1ull << b);
        }
        const unsigned long long* mrow = &g_mask[(size_t)n * PRE * 32];

        for (int w = 0; w < 32; w++) {
            int i0 = w * 64 + lane;
            int i1 = i0 + 32;
            colm[lane]      = (i0 < PRE) ? mrow[(size_t)i0 * 32 + w] : 0ull;
            colm[lane + 32] = (i1 < PRE) ? mrow[(size_t)i1 * 32 + w] : 0ull;
            __syncwarp();
            unsigned long long alivew = 0ull;
            if (lane == w) {
                unsigned long long supw = sup;
                for (int b = 0; b < 64; b++) {
                    if (!((supw >> b) & 1ull)) {
                        alivew |= (1ull << b);
                        supw |= colm[b];
                    }
                }
            }
            alivew = __shfl_sync(0xffffffffu, alivew, w);
            if (lane == w) alive_sh[w] = alivew;
            unsigned long long am = alivew, acc = 0ull;
            while (am) {
                int bb = __ffsll((long long)am) - 1;
                am &= am - 1;
                acc |= mrow[(size_t)(w * 64 + bb) * 32 + lane];
            }
            sup |= acc;
            __syncwarp();
        }

        int pc = __popcll(alive_sh[lane]);
        int xsum = pc;
        for (int off = 1; off < 32; off <<= 1) {
            int y = __shfl_up_sync(0xffffffffu, xsum, off);
            if (lane >= off) xsum += y;
        }
        base_sh[lane] = xsum - pc;
    }
    __syncthreads();

    for (int i = tid; i < PRE; i += 256) {
        int w = i >> 6, b = i & 63;
        unsigned long long aw = alive_sh[w];
        if ((aw >> b) & 1ull) {
            int rank = base_sh[w] + __popcll(aw & ((1ull << b) - 1ull));
            if (rank < POST) {
                float4 bx = *reinterpret_cast<const float4*>(&g_boxes[(size_t)(n * PRE + i) * 4]);
                float* dst = out + OFF_ROIS + (size_t)(n * POST + rank) * 4;
                dst[0] = bx.x; dst[1] = bx.y; dst[2] = bx.z; dst[3] = bx.w;
            }
        }
    }
}

// ---------------- launch ----------------
extern "C" void kernel_launch(void* const* d_in, const int* in_sizes, int n_in,
                              void* d_out, int out_size) {
    const float* feat0   = (const float*)d_in[0];
    const float* feat1   = (const float*)d_in[1];
    const float* feat2   = (const float*)d_in[2];
    const float* conv_w  = (const float*)d_in[3];
    const float* conv_b  = (const float*)d_in[4];
    const float* score_w = (const float*)d_in[5];
    const float* score_b = (const float*)d_in[6];
    const float* loc_w   = (const float*)d_in[7];
    const float* loc_b   = (const float*)d_in[8];
    const float* anchors = (const float*)d_in[9];
    float* out = (float*)d_out;

    unsigned long long *k1, *k2;
    cudaGetSymbolAddress((void**)&k1, g_keys);
    cudaGetSymbolAddress((void**)&k2, g_keys2);

    // Winograd conv pipeline (gemm is the 4th launch for ncu)
    wino_weights<<<256, 256>>>(conv_w);
    wino_input<<<2208, 256>>>(feat0, feat1, feat2);
    nop_k<<<1, 32>>>();
    wino_gemm<<<dim3(52, 2, 16), 256>>>();
    wino_output<<<T_TOTAL, 256>>>(conv_b);

    heads_kernel<<<3282, 256>>>(score_w, score_b, loc_w, loc_b, out);
    propose_kernel<<<512, 256>>>(anchors, out);

    local_sort2048<<<64, 1024>>>();
    merge_reduce<<<32, 1024>>>(k1, k2, 16);
    merge_reduce<<<16, 1024>>>(k2, k1, 8);
    merge_reduce<<< 8, 1024>>>(k1, k2, 4);
    merge_reduce<<< 4, 1024>>>(k2, k1, 2);
    merge_reduce<<< 2, 1024>>>(k1, k2, 1);

    gather_topk<<<16, 256>>>();
    nms_mask<<<dim3(250, 2), 256>>>();
    nms_finalize<<<2, 256>>>(out);

    cudaMemcpyAsync(out + OFF_ANCH, anchors, (size_t)A_TOTAL * 4 * sizeof(float),
                    cudaMemcpyDeviceToDevice, 0);
}

// round 13
// speedup vs baseline: 2.8591x; 1.0079x over previous
#include <cuda_runtime.h>
#include <math.h>
#include <stdint.h>

// ---------------- constants ----------------
#define N_IMG    2
#define A_TOTAL  39375
#define PRE      2000
#define POST     300
#define SORT_N   65536

#define OFF_LOCS    0
#define OFF_SCORES  315000
#define OFF_ROIS    472500
#define OFF_RIDX    474900
#define OFF_ANCH    475500

// Winograd tiling: per image lvl0 50x50=2500, lvl1 25x25=625, lvl2 13x13=169 tiles
#define T_PER_IMG 3294
#define T_TOTAL   6588
#define T_PAD     6656      // 52 * 128

// h (conv output, NHWC per level): lvl0 base 0, lvl1 base 5120000, lvl2 base 6400000
__device__ float               g_h[6720000];
__device__ float               g_fg[N_IMG * A_TOTAL];
__device__ float               g_roi[N_IMG * A_TOTAL * 4];
__device__ unsigned long long  g_keys[N_IMG * SORT_N];
__device__ unsigned long long  g_keys2[N_IMG * SORT_N];
__device__ float               g_boxes[N_IMG * PRE * 4];
__device__ int                 g_valid[N_IMG * PRE];
__device__ unsigned long long  g_mask[N_IMG * PRE * 32];

// Winograd buffers (g_V zero-init; pad tiles never written -> stay zero)
__device__ float               g_U[16 * 256 * 256];              // [t][ic][oc]
__device__ float               g_V[16ull * T_PAD * 256];         // [t][tile][ic]
__device__ float               g_M[16ull * T_PAD * 256];         // [t][tile][oc]

// ---------------- packed f32x2 helpers ----------------
#define FMA2(d, a, b) \
    asm("fma.rn.f32x2 %0, %1, %2, %0;" : "+l"(d) : "l"(a), "l"(b))
#define UNPACK2(lo, hi, v) \
    do { unsigned int _ulo, _uhi; \
         asm("mov.b64 {%0, %1}, %2;" : "=r"(_ulo), "=r"(_uhi) : "l"(v)); \
         lo = __uint_as_float(_ulo); hi = __uint_as_float(_uhi); } while (0)

__global__ void nop_k() {}

// ---------------- Winograd weight transform: U = G g G^T ----------------
__global__ void wino_weights(const float* __restrict__ w) {
    int p = blockIdx.x * 256 + threadIdx.x;     // 65536 = ic x oc
    int oc = p & 255, ic = p >> 8;
    const float* gw = w + ((size_t)oc * 256 + ic) * 9;
    float g0 = gw[0], g1 = gw[1], g2 = gw[2];
    float g3 = gw[3], g4 = gw[4], g5 = gw[5];
    float g6 = gw[6], g7 = gw[7], g8 = gw[8];
    float T[4][3];
    T[0][0] = g0; T[0][1] = g1; T[0][2] = g2;
    T[1][0] = 0.5f * (g0 + g3 + g6); T[1][1] = 0.5f * (g1 + g4 + g7); T[1][2] = 0.5f * (g2 + g5 + g8);
    T[2][0] = 0.5f * (g0 - g3 + g6); T[2][1] = 0.5f * (g1 - g4 + g7); T[2][2] = 0.5f * (g2 - g5 + g8);
    T[3][0] = g6; T[3][1] = g7; T[3][2] = g8;
#pragma unroll
    for (int r = 0; r < 4; r++) {
        float u0 = T[r][0];
        float u1 = 0.5f * (T[r][0] + T[r][1] + T[r][2]);
        float u2 = 0.5f * (T[r][0] - T[r][1] + T[r][2]);
        float u3 = T[r][2];
        float* dst = g_U + (size_t)(r * 4) * 65536 + (size_t)ic * 256 + oc;
        dst[0]          = u0;
        dst[1ull*65536] = u1;
        dst[2ull*65536] = u2;
        dst[3ull*65536] = u3;
    }
}

// ---------------- Winograd input transform: V = B^T d B ----------------
__global__ __launch_bounds__(256) void wino_input(const float* __restrict__ f0,
                                                  const float* __restrict__ f1,
                                                  const float* __restrict__ f2) {
    __shared__ float s[32 * 265];    // [ic] pitch 265, rows 4 x cols 66
    int b = blockIdx.x, tid = threadIdx.x;
    const float* x;
    int H, W, TW, tbase, n, icg, ty, txg;
    if (b < 1600) {
        x = f0; H = 100; W = 100; TW = 50;
        n = b / 800; int r = b % 800; icg = r / 100; int r2 = r % 100;
        ty = r2 / 2; txg = r2 % 2; tbase = n * T_PER_IMG;
    } else if (b < 2000) {
        int l = b - 1600; x = f1; H = 50; W = 50; TW = 25;
        n = l / 200; int r = l % 200; icg = r / 25; ty = r % 25; txg = 0;
        tbase = n * T_PER_IMG + 2500;
    } else {
        int l = b - 2000; x = f2; H = 25; W = 25; TW = 13;
        n = l / 104; int r = l % 104; icg = r / 13; ty = r % 13; txg = 0;
        tbase = n * T_PER_IMG + 3125;
    }
    int tx0 = txg * 32;
    int HW = H * W;
    const float* xb = x + ((size_t)n * 256 + icg * 32) * HW;

    for (int f = tid; f < 32 * 264; f += 256) {
        int ic = f / 264, rem = f % 264, row = rem / 66, col = rem % 66;
        int gy = 2 * ty - 1 + row, gx = 2 * tx0 - 1 + col;
        float v = 0.f;
        if (gy >= 0 && gy < H && gx >= 0 && gx < W)
            v = xb[(size_t)ic * HW + gy * W + gx];
        s[ic * 265 + rem] = v;
    }
    __syncthreads();

    int ntile = TW - tx0; if (ntile > 32) ntile = 32;
#pragma unroll
    for (int it = 0; it < 4; it++) {
        int wk = it * 256 + tid;
        int ici = wk & 31, tl = wk >> 5;
        if (tl >= ntile) continue;
        const float* sp = s + ici * 265 + 2 * tl;
        float d[4][4];
#pragma unroll
        for (int i = 0; i < 4; i++)
#pragma unroll
            for (int j = 0; j < 4; j++) d[i][j] = sp[i * 66 + j];
        float e[4][4];
#pragma unroll
        for (int j = 0; j < 4; j++) {
            e[0][j] = d[0][j] - d[2][j];
            e[1][j] = d[1][j] + d[2][j];
            e[2][j] = d[2][j] - d[1][j];
            e[3][j] = d[1][j] - d[3][j];
        }
        size_t tile = (size_t)(tbase + ty * TW + tx0 + tl);
        float* dst = g_V + tile * 256 + icg * 32 + ici;
#pragma unroll
        for (int r = 0; r < 4; r++) {
            float v0 = e[r][0] - e[r][2];
            float v1 = e[r][1] + e[r][2];
            float v2 = e[r][2] - e[r][1];
            float v3 = e[r][1] - e[r][3];
            dst[(size_t)(r * 4 + 0) * T_PAD * 256] = v0;
            dst[(size_t)(r * 4 + 1) * T_PAD * 256] = v1;
            dst[(size_t)(r * 4 + 2) * T_PAD * 256] = v2;
            dst[(size_t)(r * 4 + 3) * T_PAD * 256] = v3;
        }
    }
}

// ---------------- Winograd GEMM: M_t = V_t (tiles x ic) * U_t (ic x oc) ----------------
// grid (52, 2, 16): CTA = 128 tiles x 128 oc, K=256 chunks of 16; FFMA2 pairs over oc.
// Double-buffered smem (one __syncthreads per chunk); B float4-XOR swizzle; A dup-pairs.
__global__ __launch_bounds__(256, 2) void wino_gemm() {
    __shared__ __align__(16) float2 A2s[2][16 * 128];   // 32 KB
    __shared__ __align__(16) float  Bs[2][16 * 128];    // 16 KB  (total 48 KB)
    int t = threadIdx.x;
    int tz = blockIdx.z;
    int tile0 = blockIdx.x * 128;
    int oc0 = blockIdx.y * 128;
    const float* Vb = g_V + (size_t)tz * T_PAD * 256;
    const float* Ub = g_U + (size_t)tz * 65536;

    int arow = t >> 1, akq = (t & 1) * 8;
    int bidx0 = t * 2;
    int bk0 = bidx0 >> 5,       bq0 = bidx0 & 31;
    int bk1 = (bidx0 + 1) >> 5, bq1 = (bidx0 + 1) & 31;
    int bq0s = bq0 ^ ((bq0 >> 3) & 3);
    int bq1s = bq1 ^ ((bq1 >> 3) & 3);

    unsigned long long acc2[8][4];
#pragma unroll
    for (int i = 0; i < 8; i++)
#pragma unroll
        for (int j = 0; j < 4; j++) acc2[i][j] = 0ull;

    int r0 = (t >> 4) * 8;
    int qa0 = (t & 15) * 2, qa1 = qa0 + 1;
    int q0s = qa0 ^ ((qa0 >> 3) & 3);
    int q1s = qa1 ^ ((qa1 >> 3) & 3);

    // preload + stage chunk 0 into buffer 0
    {
        const float4* va = (const float4*)(Vb + (size_t)(tile0 + arow) * 256 + akq);
        float4 pa0 = va[0], pa1 = va[1];
        float4 pb0 = *(const float4*)(Ub + (size_t)bk0 * 256 + oc0 + 4 * bq0);
        float4 pb1 = *(const float4*)(Ub + (size_t)bk1 * 256 + oc0 + 4 * bq1);
        A2s[0][(akq + 0) * 128 + arow] = make_float2(pa0.x, pa0.x);
        A2s[0][(akq + 1) * 128 + arow] = make_float2(pa0.y, pa0.y);
        A2s[0][(akq + 2) * 128 + arow] = make_float2(pa0.z, pa0.z);
        A2s[0][(akq + 3) * 128 + arow] = make_float2(pa0.w, pa0.w);
        A2s[0][(akq + 4) * 128 + arow] = make_float2(pa1.x, pa1.x);
        A2s[0][(akq + 5) * 128 + arow] = make_float2(pa1.y, pa1.y);
        A2s[0][(akq + 6) * 128 + arow] = make_float2(pa1.z, pa1.z);
        A2s[0][(akq + 7) * 128 + arow] = make_float2(pa1.w, pa1.w);
        *(float4*)&Bs[0][bk0 * 128 + 4 * bq0s] = pb0;
        *(float4*)&Bs[0][bk1 * 128 + 4 * bq1s] = pb1;
    }
    __syncthreads();

    int buf = 0;
    for (int k0 = 0; k0 < 256; k0 += 16) {
        // prefetch next chunk into registers (latency hidden by compute below)
        float4 pa0, pa1, pb0, pb1;
        bool more = (k0 + 16 < 256);
        if (more) {
            const float4* van = (const float4*)(Vb + (size_t)(tile0 + arow) * 256 + (k0 + 16) + akq);
            pa0 = van[0]; pa1 = van[1];
            pb0 = *(const float4*)(Ub + (size_t)(k0 + 16 + bk0) * 256 + oc0 + 4 * bq0);
            pb1 = *(const float4*)(Ub + (size_t)(k0 + 16 + bk1) * 256 + oc0 + 4 * bq1);
        }

        // compute chunk from current buffer
        const float2* Ab = A2s[buf];
        const float*  Bb = Bs[buf];
#pragma unroll
        for (int k = 0; k < 16; k++) {
            ulonglong2 aw0 = *(const ulonglong2*)&Ab[k * 128 + r0 + 0];
            ulonglong2 aw1 = *(const ulonglong2*)&Ab[k * 128 + r0 + 2];
            ulonglong2 aw2 = *(const ulonglong2*)&Ab[k * 128 + r0 + 4];
            ulonglong2 aw3 = *(const ulonglong2*)&Ab[k * 128 + r0 + 6];
            ulonglong2 bw0 = *(const ulonglong2*)&Bb[k * 128 + 4 * q0s];
            ulonglong2 bw1 = *(const ulonglong2*)&Bb[k * 128 + 4 * q1s];
            unsigned long long a2[8] = {aw0.x, aw0.y, aw1.x, aw1.y,
                                        aw2.x, aw2.y, aw3.x, aw3.y};
            unsigned long long b2[4] = {bw0.x, bw0.y, bw1.x, bw1.y};
#pragma unroll
            for (int i = 0; i < 8; i++)
#pragma unroll
                for (int j = 0; j < 4; j++)
                    FMA2(acc2[i][j], a2[i], b2[j]);
        }

        // stage next chunk into the other buffer, one sync per chunk
        if (more) {
            int nb = buf ^ 1;
            A2s[nb][(akq + 0) * 128 + arow] = make_float2(pa0.x, pa0.x);
            A2s[nb][(akq + 1) * 128 + arow] = make_float2(pa0.y, pa0.y);
            A2s[nb][(akq + 2) * 128 + arow] = make_float2(pa0.z, pa0.z);
            A2s[nb][(akq + 3) * 128 + arow] = make_float2(pa0.w, pa0.w);
            A2s[nb][(akq + 4) * 128 + arow] = make_float2(pa1.x, pa1.x);
            A2s[nb][(akq + 5) * 128 + arow] = make_float2(pa1.y, pa1.y);
            A2s[nb][(akq + 6) * 128 + arow] = make_float2(pa1.z, pa1.z);
            A2s[nb][(akq + 7) * 128 + arow] = make_float2(pa1.w, pa1.w);
            *(float4*)&Bs[nb][bk0 * 128 + 4 * bq0s] = pb0;
            *(float4*)&Bs[nb][bk1 * 128 + 4 * bq1s] = pb1;
            __syncthreads();
        }
        buf ^= 1;
    }

    // epilogue
    int c0 = (t & 15) * 8;
#pragma unroll
    for (int i = 0; i < 8; i++) {
        float v[8];
#pragma unroll
        for (int j = 0; j < 4; j++) UNPACK2(v[2 * j], v[2 * j + 1], acc2[i][j]);
        float* dst = g_M + (size_t)tz * T_PAD * 256 + (size_t)(tile0 + r0 + i) * 256 + oc0 + c0;
        *(float4*)dst       = make_float4(v[0], v[1], v[2], v[3]);
        *(float4*)(dst + 4) = make_float4(v[4], v[5], v[6], v[7]);
    }
}

// ---------------- Winograd output transform: Y = A^T M A + bias, relu ----------------
__global__ __launch_bounds__(256) void wino_output(const float* __restrict__ bias) {
    int tile = blockIdx.x;          // 0..6587
    int oc = threadIdx.x;
    int n = tile / T_PER_IMG, r = tile % T_PER_IMG;
    int hoff, H, W, TW, lbase;
    if (r < 2500)      { hoff = 0;       H = 100; W = 100; TW = 50; lbase = 0; }
    else if (r < 3125) { hoff = 5120000; H = 50;  W = 50;  TW = 25; lbase = 2500; }
    else               { hoff = 6400000; H = 25;  W = 25;  TW = 13; lbase = 3125; }
    int lt = r - lbase, ty = lt / TW, tx = lt % TW;

    float m[16];
    const float* Mp = g_M + (size_t)tile * 256 + oc;
#pragma unroll
    for (int i = 0; i < 16; i++) m[i] = Mp[(size_t)i * T_PAD * 256];

    float e0[4], e1[4];
#pragma unroll
    for (int j = 0; j < 4; j++) {
        e0[j] = m[0 * 4 + j] + m[1 * 4 + j] + m[2 * 4 + j];
        e1[j] = m[1 * 4 + j] - m[2 * 4 + j] - m[3 * 4 + j];
    }
    float bv = bias[oc];
    float o00 = fmaxf(e0[0] + e0[1] + e0[2] + bv, 0.f);
    float o01 = fmaxf(e0[1] - e0[2] - e0[3] + bv, 0.f);
    float o10 = fmaxf(e1[0] + e1[1] + e1[2] + bv, 0.f);
    float o11 = fmaxf(e1[1] - e1[2] - e1[3] + bv, 0.f);

    int HW = H * W;
    int py = 2 * ty, px = 2 * tx;
    float* base = g_h + hoff + (size_t)n * HW * 256;
    if (py < H && px < W)         base[((size_t)(py * W + px)) * 256 + oc]           = o00;
    if (py < H && px + 1 < W)     base[((size_t)(py * W + px + 1)) * 256 + oc]       = o01;
    if (py + 1 < H && px < W)     base[((size_t)((py + 1) * W + px)) * 256 + oc]     = o10;
    if (py + 1 < H && px + 1 < W) base[((size_t)((py + 1) * W + px + 1)) * 256 + oc] = o11;
}

// ---------------- heads: 18x256 projections + softmax fg ----------------
__global__ __launch_bounds__(256)
void heads_kernel(const float* __restrict__ score_w, const float* __restrict__ score_b,
                  const float* __restrict__ loc_w, const float* __restrict__ loc_b,
                  float* __restrict__ out) {
    __shared__ float s_w[18 * 256];
    __shared__ float s_b[18];
    int tid = threadIdx.x;
    for (int i = tid; i < 6 * 256; i += 256)  s_w[i] = score_w[i];
    for (int i = tid; i < 12 * 256; i += 256) s_w[6 * 256 + i] = loc_w[i];
    if (tid < 6)       s_b[tid] = score_b[tid];
    else if (tid < 18) s_b[tid] = loc_b[tid - 6];
    __syncthreads();

    int warp = tid >> 5, lane = tid & 31;
    int P = blockIdx.x * 8 + warp;
    if (P >= 26250) return;
    int n = P / 13125;
    int p = P % 13125;
    int aoff, hbase, ploc;
    if (p < 10000)      { ploc = p;         aoff = 0;     hbase = n * 2560000 + ploc * 256; }
    else if (p < 12500) { ploc = p - 10000; aoff = 30000; hbase = 5120000 + n * 640000 + ploc * 256; }
    else                { ploc = p - 12500; aoff = 37500; hbase = 6400000 + n * 160000 + ploc * 256; }

    const float4* hp = reinterpret_cast<const float4*>(&g_h[hbase]);
    float4 v0 = hp[lane];
    float4 v1 = hp[lane + 32];
    float hv[8] = {v0.x, v0.y, v0.z, v0.w, v1.x, v1.y, v1.z, v1.w};

    float res[18];
#pragma unroll
    for (int o = 0; o < 18; o++) {
        const float* wr = &s_w[o * 256];
        float4 wa = *reinterpret_cast<const float4*>(&wr[lane * 4]);
        float4 wb = *reinterpret_cast<const float4*>(&wr[128 + lane * 4]);
        float s = hv[0] * wa.x + hv[1] * wa.y + hv[2] * wa.z + hv[3] * wa.w +
                  hv[4] * wb.x + hv[5] * wb.y + hv[6] * wb.z + hv[7] * wb.w;
#pragma unroll
        for (int off = 16; off; off >>= 1) s += __shfl_xor_sync(0xffffffffu, s, off);
        res[o] = s + s_b[o];
    }

    if (lane == 0) {
        int aid0 = aoff + ploc * 3;
#pragma unroll
        for (int a = 0; a < 3; a++) {
            int aid = aid0 + a;
            float s0 = res[a * 2 + 0], s1 = res[a * 2 + 1];
            out[OFF_SCORES + (size_t)(n * A_TOTAL + aid) * 2 + 0] = s0;
            out[OFF_SCORES + (size_t)(n * A_TOTAL + aid) * 2 + 1] = s1;
            g_fg[n * A_TOTAL + aid] = 1.f / (1.f + expf(s0 - s1));
#pragma unroll
            for (int c = 0; c < 4; c++)
                out[OFF_LOCS + (size_t)(n * A_TOTAL + aid) * 4 + c] = res[6 + a * 4 + c];
        }
    }
}

// ---------------- propose: loc2bbox + clip + valid + sort key ----------------
__device__ __forceinline__ unsigned int flip_f(float f) {
    unsigned int b = __float_as_uint(f);
    return (b & 0x80000000u) ? ~b : (b | 0x80000000u);
}

__global__ void propose_kernel(const float* __restrict__ anchors, const float* __restrict__ out) {
    int t = blockIdx.x * 256 + threadIdx.x;
    if (t >= N_IMG * SORT_N) return;
    int n = t / SORT_N, s = t % SORT_N;
    unsigned long long key = ~0ull;
    if (s < A_TOTAL) {
        float4 lc = *reinterpret_cast<const float4*>(out + OFF_LOCS + (size_t)(n * A_TOTAL + s) * 4);
        float4 an = *reinterpret_cast<const float4*>(anchors + (size_t)s * 4);
        float sh = an.z - an.x, sw = an.w - an.y;
        float cy = an.x + 0.5f * sh, cx = an.y + 0.5f * sw;
        float ncy = lc.x * sh + cy, ncx = lc.y * sw + cx;
        float nh = expf(lc.z) * sh, nw = expf(lc.w) * sw;
        float y1 = fminf(fmaxf(ncy - 0.5f * nh, 0.f), 800.f);
        float x1 = fminf(fmaxf(ncx - 0.5f * nw, 0.f), 800.f);
        float y2 = fminf(fmaxf(ncy + 0.5f * nh, 0.f), 800.f);
        float x2 = fminf(fmaxf(ncx + 0.5f * nw, 0.f), 800.f);
        float4 r = make_float4(y1, x1, y2, x2);
        *reinterpret_cast<float4*>(&g_roi[(size_t)(n * A_TOTAL + s) * 4]) = r;
        bool valid = ((y2 - y1) >= 16.f) && ((x2 - x1) >= 16.f);
        float sc = valid ? g_fg[n * A_TOTAL + s] : -INFINITY;
        unsigned int u = flip_f(sc);
        key = ((unsigned long long)(~u) << 32) | (unsigned int)s;
    }
    g_keys[t] = key;
}

// ---------------- local sort: each 2048-run ascending ----------------
__global__ __launch_bounds__(1024) void local_sort2048() {
    __shared__ unsigned long long sm[2048];
    int base = blockIdx.x * 2048;
    int tid = threadIdx.x;
    sm[tid] = g_keys[base + tid];
    sm[tid + 1024] = g_keys[base + tid + 1024];
    __syncthreads();
    for (int k = 2; k <= 2048; k <<= 1) {
        for (int j = k >> 1; j > 0; j >>= 1) {
            int i1 = ((tid / j) * 2 * j) + (tid % j);
            int i2 = i1 + j;
            bool dir = ((i1 & k) == 0);
            unsigned long long a = sm[i1], b = sm[i2];
            if (dir ? (a > b) : (a < b)) { sm[i1] = b; sm[i2] = a; }
            __syncthreads();
        }
    }
    g_keys[base + tid] = sm[tid];
    g_keys[base + tid + 1024] = sm[tid + 1024];
}

// ---------------- tournament merge-reduce ----------------
__global__ __launch_bounds__(1024) void merge_reduce(const unsigned long long* __restrict__ in,
                                                     unsigned long long* __restrict__ outb,
                                                     int runs_out_per_img) {
    __shared__ unsigned long long sm[2048];
    int img = blockIdx.x / runs_out_per_img;
    int r   = blockIdx.x % runs_out_per_img;
    const unsigned long long* A = in + (size_t)img * SORT_N + (size_t)(2 * r) * 2048;
    const unsigned long long* B = A + 2048;
    int tid = threadIdx.x;
    {
        unsigned long long a0 = A[tid],        b0 = B[2047 - tid];
        unsigned long long a1 = A[tid + 1024], b1 = B[1023 - tid];
        sm[tid]        = a0 < b0 ? a0 : b0;
        sm[tid + 1024] = a1 < b1 ? a1 : b1;
    }
    __syncthreads();
    for (int j = 1024; j > 0; j >>= 1) {
        int i1 = ((tid / j) * 2 * j) + (tid % j);
        int i2 = i1 + j;
        unsigned long long a = sm[i1], b = sm[i2];
        if (a > b) { sm[i1] = b; sm[i2] = a; }
        __syncthreads();
    }
    unsigned long long* O = outb + (size_t)img * SORT_N + (size_t)r * 2048;
    O[tid] = sm[tid];
    O[tid + 1024] = sm[tid + 1024];
}

// ---------------- gather top-2000 boxes ----------------
__global__ void gather_topk() {
    int t = blockIdx.x * 256 + threadIdx.x;
    if (t >= N_IMG * PRE) return;
    int n = t / PRE, r = t % PRE;
    unsigned long long key = g_keys2[(size_t)n * SORT_N + r];
    unsigned int hi = (unsigned int)(key >> 32);
    int valid = hi < 0xFF800000u;
    unsigned int idx = (unsigned int)key;
    float4 bx = make_float4(0.f, 0.f, 0.f, 0.f);
    if (idx < A_TOTAL)
        bx = *reinterpret_cast<const float4*>(&g_roi[(size_t)(n * A_TOTAL + idx) * 4]);
    *reinterpret_cast<float4*>(&g_boxes[(size_t)t * 4]) = bx;
    g_valid[t] = valid;
}

// ---------------- NMS suppression bitmask ----------------
__global__ void nms_mask() {
    int t = blockIdx.x * 256 + threadIdx.x;
    int n = blockIdx.y;
    if (t >= PRE * 32) return;
    int i = t >> 5, w = t & 31;
    const float4 bi = *reinterpret_cast<const float4*>(&g_boxes[(size_t)(n * PRE + i) * 4]);
    float area_i = (bi.z - bi.x) * (bi.w - bi.y);
    unsigned long long m = 0ull;
    int j0 = w * 64;
    for (int b = 0; b < 64; b++) {
        int j = j0 + b;
        if (j <= i || j >= PRE) continue;
        float4 bj = *reinterpret_cast<const float4*>(&g_boxes[(size_t)(n * PRE + j) * 4]);
        float ty = fmaxf(bi.x, bj.x), txx = fmaxf(bi.y, bj.y);
        float by = fminf(bi.z, bj.z), bxx = fminf(bi.w, bj.w);
        float hh = fmaxf(by - ty, 0.f), ww = fmaxf(bxx - txx, 0.f);
        float inter = hh * ww;
        float area_j = (bj.z - bj.x) * (bj.w - bj.y);
        float iou = inter / (area_i + area_j - inter + 1e-12f);
        if (iou > 0.7f) m |= (1ull << b);
    }
    g_mask[((size_t)n * PRE + i) * 32 + w] = m;
}

// ---------------- greedy NMS reduce (word-wise) + parallel emit ----------------
__global__ void nms_finalize(float* __restrict__ out) {
    int n = blockIdx.x;
    int tid = threadIdx.x;
    __shared__ unsigned long long alive_sh[32];
    __shared__ unsigned long long colm[64];
    __shared__ int base_sh[32];

    for (int i = tid; i < POST * 4; i += 256) out[OFF_ROIS + (size_t)n * POST * 4 + i] = 0.f;
    for (int i = tid; i < POST; i += 256)     out[OFF_RIDX + (size_t)n * POST + i] = (float)n;
    __syncthreads();

    if (tid < 32) {
        int lane = tid;
        unsigned long long sup = 0ull;
        for (int b = 0; b < 64; b++) {
            int i = lane * 64 + b;
            if (i >= PRE || !g_valid[n * PRE + i]) sup |= (1ull << b);
        }
        const unsigned long long* mrow = &g_mask[(size_t)n * PRE * 32];

        for (int w = 0; w < 32; w++) {
            int i0 = w * 64 + lane;
            int i1 = i0 + 32;
            colm[lane]      = (i0 < PRE) ? mrow[(size_t)i0 * 32 + w] : 0ull;
            colm[lane + 32] = (i1 < PRE) ? mrow[(size_t)i1 * 32 + w] : 0ull;
            __syncwarp();
            unsigned long long alivew = 0ull;
            if (lane == w) {
                unsigned long long supw = sup;
                for (int b = 0; b < 64; b++) {
                    if (!((supw >> b) & 1ull)) {
                        alivew |= (1ull << b);
                        supw |= colm[b];
                    }
                }
            }
            alivew = __shfl_sync(0xffffffffu, alivew, w);
            if (lane == w) alive_sh[w] = alivew;
            unsigned long long am = alivew, acc = 0ull;
            while (am) {
                int bb = __ffsll((long long)am) - 1;
                am &= am - 1;
                acc |= mrow[(size_t)(w * 64 + bb) * 32 + lane];
            }
            sup |= acc;
            __syncwarp();
        }

        int pc = __popcll(alive_sh[lane]);
        int xsum = pc;
        for (int off = 1; off < 32; off <<= 1) {
            int y = __shfl_up_sync(0xffffffffu, xsum, off);
            if (lane >= off) xsum += y;
        }
        base_sh[lane] = xsum - pc;
    }
    __syncthreads();

    for (int i = tid; i < PRE; i += 256) {
        int w = i >> 6, b = i & 63;
        unsigned long long aw = alive_sh[w];
        if ((aw >> b) & 1ull) {
            int rank = base_sh[w] + __popcll(aw & ((1ull << b) - 1ull));
            if (rank < POST) {
                float4 bx = *reinterpret_cast<const float4*>(&g_boxes[(size_t)(n * PRE + i) * 4]);
                float* dst = out + OFF_ROIS + (size_t)(n * POST + rank) * 4;
                dst[0] = bx.x; dst[1] = bx.y; dst[2] = bx.z; dst[3] = bx.w;
            }
        }
    }
}

// ---------------- launch ----------------
extern "C" void kernel_launch(void* const* d_in, const int* in_sizes, int n_in,
                              void* d_out, int out_size) {
    const float* feat0   = (const float*)d_in[0];
    const float* feat1   = (const float*)d_in[1];
    const float* feat2   = (const float*)d_in[2];
    const float* conv_w  = (const float*)d_in[3];
    const float* conv_b  = (const float*)d_in[4];
    const float* score_w = (const float*)d_in[5];
    const float* score_b = (const float*)d_in[6];
    const float* loc_w   = (const float*)d_in[7];
    const float* loc_b   = (const float*)d_in[8];
    const float* anchors = (const float*)d_in[9];
    float* out = (float*)d_out;

    unsigned long long *k1, *k2;
    cudaGetSymbolAddress((void**)&k1, g_keys);
    cudaGetSymbolAddress((void**)&k2, g_keys2);

    // Winograd conv pipeline (gemm is the 4th launch for ncu)
    wino_weights<<<256, 256>>>(conv_w);
    wino_input<<<2208, 256>>>(feat0, feat1, feat2);
    nop_k<<<1, 32>>>();
    wino_gemm<<<dim3(52, 2, 16), 256>>>();
    wino_output<<<T_TOTAL, 256>>>(conv_b);

    heads_kernel<<<3282, 256>>>(score_w, score_b, loc_w, loc_b, out);
    propose_kernel<<<512, 256>>>(anchors, out);

    local_sort2048<<<64, 1024>>>();
    merge_reduce<<<32, 1024>>>(k1, k2, 16);
    merge_reduce<<<16, 1024>>>(k2, k1, 8);
    merge_reduce<<< 8, 1024>>>(k1, k2, 4);
    merge_reduce<<< 4, 1024>>>(k2, k1, 2);
    merge_reduce<<< 2, 1024>>>(k1, k2, 1);

    gather_topk<<<16, 256>>>();
    nms_mask<<<dim3(250, 2), 256>>>();
    nms_finalize<<<2, 256>>>(out);

    cudaMemcpyAsync(out + OFF_ANCH, anchors, (size_t)A_TOTAL * 4 * sizeof(float),
                    cudaMemcpyDeviceToDevice, 0);
}

// round 14
// speedup vs baseline: 2.8676x; 1.0030x over previous
#include <cuda_runtime.h>
#include <math.h>
#include <stdint.h>

// ---------------- constants ----------------
#define N_IMG    2
#define A_TOTAL  39375
#define PRE      2000
#define POST     300
#define SORT_N   65536

#define OFF_LOCS    0
#define OFF_SCORES  315000
#define OFF_ROIS    472500
#define OFF_RIDX    474900
#define OFF_ANCH    475500

// Winograd tiling: per image lvl0 50x50=2500, lvl1 25x25=625, lvl2 13x13=169 tiles
#define T_PER_IMG 3294
#define T_TOTAL   6588
#define T_PAD     6656      // 52 * 128

// h (conv output, NHWC per level): lvl0 base 0, lvl1 base 5120000, lvl2 base 6400000
__device__ float               g_h[6720000];
__device__ float               g_fg[N_IMG * A_TOTAL];
__device__ float               g_roi[N_IMG * A_TOTAL * 4];
__device__ unsigned long long  g_keys[N_IMG * SORT_N];
__device__ unsigned long long  g_keys2[N_IMG * SORT_N];
__device__ float               g_boxes[N_IMG * PRE * 4];
__device__ int                 g_valid[N_IMG * PRE];
__device__ unsigned long long  g_mask[N_IMG * PRE * 32];

// Winograd buffers (g_V zero-init; pad tiles never written -> stay zero)
__device__ float               g_U[16 * 256 * 256];              // [t][ic][oc]
__device__ float               g_V[16ull * T_PAD * 256];         // [t][tile][ic]
__device__ float               g_M[16ull * T_PAD * 256];         // [t][tile][oc]

// ---------------- packed f32x2 helpers ----------------
#define FMA2(d, a, b) \
    asm("fma.rn.f32x2 %0, %1, %2, %0;" : "+l"(d) : "l"(a), "l"(b))
#define UNPACK2(lo, hi, v) \
    do { unsigned int _ulo, _uhi; \
         asm("mov.b64 {%0, %1}, %2;" : "=r"(_ulo), "=r"(_uhi) : "l"(v)); \
         lo = __uint_as_float(_ulo); hi = __uint_as_float(_uhi); } while (0)

// ---------------- Winograd weight transform: U = G g G^T ----------------
__global__ void wino_weights(const float* __restrict__ w) {
    int p = blockIdx.x * 256 + threadIdx.x;     // 65536 = ic x oc
    int oc = p & 255, ic = p >> 8;
    const float* gw = w + ((size_t)oc * 256 + ic) * 9;
    float g0 = gw[0], g1 = gw[1], g2 = gw[2];
    float g3 = gw[3], g4 = gw[4], g5 = gw[5];
    float g6 = gw[6], g7 = gw[7], g8 = gw[8];
    float T[4][3];
    T[0][0] = g0; T[0][1] = g1; T[0][2] = g2;
    T[1][0] = 0.5f * (g0 + g3 + g6); T[1][1] = 0.5f * (g1 + g4 + g7); T[1][2] = 0.5f * (g2 + g5 + g8);
    T[2][0] = 0.5f * (g0 - g3 + g6); T[2][1] = 0.5f * (g1 - g4 + g7); T[2][2] = 0.5f * (g2 - g5 + g8);
    T[3][0] = g6; T[3][1] = g7; T[3][2] = g8;
#pragma unroll
    for (int r = 0; r < 4; r++) {
        float u0 = T[r][0];
        float u1 = 0.5f * (T[r][0] + T[r][1] + T[r][2]);
        float u2 = 0.5f * (T[r][0] - T[r][1] + T[r][2]);
        float u3 = T[r][2];
        float* dst = g_U + (size_t)(r * 4) * 65536 + (size_t)ic * 256 + oc;
        dst[0]          = u0;
        dst[1ull*65536] = u1;
        dst[2ull*65536] = u2;
        dst[3ull*65536] = u3;
    }
}

// ---------------- Winograd input transform: V = B^T d B ----------------
__global__ __launch_bounds__(256) void wino_input(const float* __restrict__ f0,
                                                  const float* __restrict__ f1,
                                                  const float* __restrict__ f2) {
    __shared__ float s[32 * 265];    // [ic] pitch 265, rows 4 x cols 66
    int b = blockIdx.x, tid = threadIdx.x;
    const float* x;
    int H, W, TW, tbase, n, icg, ty, txg;
    if (b < 1600) {
        x = f0; H = 100; W = 100; TW = 50;
        n = b / 800; int r = b % 800; icg = r / 100; int r2 = r % 100;
        ty = r2 / 2; txg = r2 % 2; tbase = n * T_PER_IMG;
    } else if (b < 2000) {
        int l = b - 1600; x = f1; H = 50; W = 50; TW = 25;
        n = l / 200; int r = l % 200; icg = r / 25; ty = r % 25; txg = 0;
        tbase = n * T_PER_IMG + 2500;
    } else {
        int l = b - 2000; x = f2; H = 25; W = 25; TW = 13;
        n = l / 104; int r = l % 104; icg = r / 13; ty = r % 13; txg = 0;
        tbase = n * T_PER_IMG + 3125;
    }
    int tx0 = txg * 32;
    int HW = H * W;
    const float* xb = x + ((size_t)n * 256 + icg * 32) * HW;

    for (int f = tid; f < 32 * 264; f += 256) {
        int ic = f / 264, rem = f % 264, row = rem / 66, col = rem % 66;
        int gy = 2 * ty - 1 + row, gx = 2 * tx0 - 1 + col;
        float v = 0.f;
        if (gy >= 0 && gy < H && gx >= 0 && gx < W)
            v = xb[(size_t)ic * HW + gy * W + gx];
        s[ic * 265 + rem] = v;
    }
    __syncthreads();

    int ntile = TW - tx0; if (ntile > 32) ntile = 32;
#pragma unroll
    for (int it = 0; it < 4; it++) {
        int wk = it * 256 + tid;
        int ici = wk & 31, tl = wk >> 5;
        if (tl >= ntile) continue;
        const float* sp = s + ici * 265 + 2 * tl;
        float d[4][4];
#pragma unroll
        for (int i = 0; i < 4; i++)
#pragma unroll
            for (int j = 0; j < 4; j++) d[i][j] = sp[i * 66 + j];
        float e[4][4];
#pragma unroll
        for (int j = 0; j < 4; j++) {
            e[0][j] = d[0][j] - d[2][j];
            e[1][j] = d[1][j] + d[2][j];
            e[2][j] = d[2][j] - d[1][j];
            e[3][j] = d[1][j] - d[3][j];
        }
        size_t tile = (size_t)(tbase + ty * TW + tx0 + tl);
        float* dst = g_V + tile * 256 + icg * 32 + ici;
#pragma unroll
        for (int r = 0; r < 4; r++) {
            float v0 = e[r][0] - e[r][2];
            float v1 = e[r][1] + e[r][2];
            float v2 = e[r][2] - e[r][1];
            float v3 = e[r][1] - e[r][3];
            dst[(size_t)(r * 4 + 0) * T_PAD * 256] = v0;
            dst[(size_t)(r * 4 + 1) * T_PAD * 256] = v1;
            dst[(size_t)(r * 4 + 2) * T_PAD * 256] = v2;
            dst[(size_t)(r * 4 + 3) * T_PAD * 256] = v3;
        }
    }
}

// ---------------- Winograd GEMM: M_t = V_t (tiles x ic) * U_t (ic x oc) ----------------
__global__ __launch_bounds__(256, 2) void wino_gemm() {
    __shared__ __align__(16) float2 A2s[2][16 * 128];   // 32 KB
    __shared__ __align__(16) float  Bs[2][16 * 128];    // 16 KB  (total 48 KB)
    int t = threadIdx.x;
    int tz = blockIdx.z;
    int tile0 = blockIdx.x * 128;
    int oc0 = blockIdx.y * 128;
    const float* Vb = g_V + (size_t)tz * T_PAD * 256;
    const float* Ub = g_U + (size_t)tz * 65536;

    int arow = t >> 1, akq = (t & 1) * 8;
    int bidx0 = t * 2;
    int bk0 = bidx0 >> 5,       bq0 = bidx0 & 31;
    int bk1 = (bidx0 + 1) >> 5, bq1 = (bidx0 + 1) & 31;
    int bq0s = bq0 ^ ((bq0 >> 3) & 3);
    int bq1s = bq1 ^ ((bq1 >> 3) & 3);

    unsigned long long acc2[8][4];
#pragma unroll
    for (int i = 0; i < 8; i++)
#pragma unroll
        for (int j = 0; j < 4; j++) acc2[i][j] = 0ull;

    int r0 = (t >> 4) * 8;
    int qa0 = (t & 15) * 2, qa1 = qa0 + 1;
    int q0s = qa0 ^ ((qa0 >> 3) & 3);
    int q1s = qa1 ^ ((qa1 >> 3) & 3);

    {
        const float4* va = (const float4*)(Vb + (size_t)(tile0 + arow) * 256 + akq);
        float4 pa0 = va[0], pa1 = va[1];
        float4 pb0 = *(const float4*)(Ub + (size_t)bk0 * 256 + oc0 + 4 * bq0);
        float4 pb1 = *(const float4*)(Ub + (size_t)bk1 * 256 + oc0 + 4 * bq1);
        A2s[0][(akq + 0) * 128 + arow] = make_float2(pa0.x, pa0.x);
        A2s[0][(akq + 1) * 128 + arow] = make_float2(pa0.y, pa0.y);
        A2s[0][(akq + 2) * 128 + arow] = make_float2(pa0.z, pa0.z);
        A2s[0][(akq + 3) * 128 + arow] = make_float2(pa0.w, pa0.w);
        A2s[0][(akq + 4) * 128 + arow] = make_float2(pa1.x, pa1.x);
        A2s[0][(akq + 5) * 128 + arow] = make_float2(pa1.y, pa1.y);
        A2s[0][(akq + 6) * 128 + arow] = make_float2(pa1.z, pa1.z);
        A2s[0][(akq + 7) * 128 + arow] = make_float2(pa1.w, pa1.w);
        *(float4*)&Bs[0][bk0 * 128 + 4 * bq0s] = pb0;
        *(float4*)&Bs[0][bk1 * 128 + 4 * bq1s] = pb1;
    }
    __syncthreads();

    int buf = 0;
    for (int k0 = 0; k0 < 256; k0 += 16) {
        float4 pa0, pa1, pb0, pb1;
        bool more = (k0 + 16 < 256);
        if (more) {
            const float4* van = (const float4*)(Vb + (size_t)(tile0 + arow) * 256 + (k0 + 16) + akq);
            pa0 = van[0]; pa1 = van[1];
            pb0 = *(const float4*)(Ub + (size_t)(k0 + 16 + bk0) * 256 + oc0 + 4 * bq0);
            pb1 = *(const float4*)(Ub + (size_t)(k0 + 16 + bk1) * 256 + oc0 + 4 * bq1);
        }

        const float2* Ab = A2s[buf];
        const float*  Bb = Bs[buf];
#pragma unroll
        for (int k = 0; k < 16; k++) {
            ulonglong2 aw0 = *(const ulonglong2*)&Ab[k * 128 + r0 + 0];
            ulonglong2 aw1 = *(const ulonglong2*)&Ab[k * 128 + r0 + 2];
            ulonglong2 aw2 = *(const ulonglong2*)&Ab[k * 128 + r0 + 4];
            ulonglong2 aw3 = *(const ulonglong2*)&Ab[k * 128 + r0 + 6];
            ulonglong2 bw0 = *(const ulonglong2*)&Bb[k * 128 + 4 * q0s];
            ulonglong2 bw1 = *(const ulonglong2*)&Bb[k * 128 + 4 * q1s];
            unsigned long long a2[8] = {aw0.x, aw0.y, aw1.x, aw1.y,
                                        aw2.x, aw2.y, aw3.x, aw3.y};
            unsigned long long b2[4] = {bw0.x, bw0.y, bw1.x, bw1.y};
#pragma unroll
            for (int i = 0; i < 8; i++)
#pragma unroll
                for (int j = 0; j < 4; j++)
                    FMA2(acc2[i][j], a2[i], b2[j]);
        }

        if (more) {
            int nb = buf ^ 1;
            A2s[nb][(akq + 0) * 128 + arow] = make_float2(pa0.x, pa0.x);
            A2s[nb][(akq + 1) * 128 + arow] = make_float2(pa0.y, pa0.y);
            A2s[nb][(akq + 2) * 128 + arow] = make_float2(pa0.z, pa0.z);
            A2s[nb][(akq + 3) * 128 + arow] = make_float2(pa0.w, pa0.w);
            A2s[nb][(akq + 4) * 128 + arow] = make_float2(pa1.x, pa1.x);
            A2s[nb][(akq + 5) * 128 + arow] = make_float2(pa1.y, pa1.y);
            A2s[nb][(akq + 6) * 128 + arow] = make_float2(pa1.z, pa1.z);
            A2s[nb][(akq + 7) * 128 + arow] = make_float2(pa1.w, pa1.w);
            *(float4*)&Bs[nb][bk0 * 128 + 4 * bq0s] = pb0;
            *(float4*)&Bs[nb][bk1 * 128 + 4 * bq1s] = pb1;
            __syncthreads();
        }
        buf ^= 1;
    }

    int c0 = (t & 15) * 8;
#pragma unroll
    for (int i = 0; i < 8; i++) {
        float v[8];
#pragma unroll
        for (int j = 0; j < 4; j++) UNPACK2(v[2 * j], v[2 * j + 1], acc2[i][j]);
        float* dst = g_M + (size_t)tz * T_PAD * 256 + (size_t)(tile0 + r0 + i) * 256 + oc0 + c0;
        *(float4*)dst       = make_float4(v[0], v[1], v[2], v[3]);
        *(float4*)(dst + 4) = make_float4(v[4], v[5], v[6], v[7]);
    }
}

// ---------------- Winograd output transform: Y = A^T M A + bias, relu ----------------
__global__ __launch_bounds__(256) void wino_output(const float* __restrict__ bias) {
    int tile = blockIdx.x;          // 0..6587
    int oc = threadIdx.x;
    int n = tile / T_PER_IMG, r = tile % T_PER_IMG;
    int hoff, H, W, TW, lbase;
    if (r < 2500)      { hoff = 0;       H = 100; W = 100; TW = 50; lbase = 0; }
    else if (r < 3125) { hoff = 5120000; H = 50;  W = 50;  TW = 25; lbase = 2500; }
    else               { hoff = 6400000; H = 25;  W = 25;  TW = 13; lbase = 3125; }
    int lt = r - lbase, ty = lt / TW, tx = lt % TW;

    float m[16];
    const float* Mp = g_M + (size_t)tile * 256 + oc;
#pragma unroll
    for (int i = 0; i < 16; i++) m[i] = Mp[(size_t)i * T_PAD * 256];

    float e0[4], e1[4];
#pragma unroll
    for (int j = 0; j < 4; j++) {
        e0[j] = m[0 * 4 + j] + m[1 * 4 + j] + m[2 * 4 + j];
        e1[j] = m[1 * 4 + j] - m[2 * 4 + j] - m[3 * 4 + j];
    }
    float bv = bias[oc];
    float o00 = fmaxf(e0[0] + e0[1] + e0[2] + bv, 0.f);
    float o01 = fmaxf(e0[1] - e0[2] - e0[3] + bv, 0.f);
    float o10 = fmaxf(e1[0] + e1[1] + e1[2] + bv, 0.f);
    float o11 = fmaxf(e1[1] - e1[2] - e1[3] + bv, 0.f);

    int HW = H * W;
    int py = 2 * ty, px = 2 * tx;
    float* base = g_h + hoff + (size_t)n * HW * 256;
    if (py < H && px < W)         base[((size_t)(py * W + px)) * 256 + oc]           = o00;
    if (py < H && px + 1 < W)     base[((size_t)(py * W + px + 1)) * 256 + oc]       = o01;
    if (py + 1 < H && px < W)     base[((size_t)((py + 1) * W + px)) * 256 + oc]     = o10;
    if (py + 1 < H && px + 1 < W) base[((size_t)((py + 1) * W + px + 1)) * 256 + oc] = o11;
}

// ---------------- heads: 18x256 projections + softmax fg ----------------
__global__ __launch_bounds__(256)
void heads_kernel(const float* __restrict__ score_w, const float* __restrict__ score_b,
                  const float* __restrict__ loc_w, const float* __restrict__ loc_b,
                  float* __restrict__ out) {
    __shared__ float s_w[18 * 256];
    __shared__ float s_b[18];
    int tid = threadIdx.x;
    for (int i = tid; i < 6 * 256; i += 256)  s_w[i] = score_w[i];
    for (int i = tid; i < 12 * 256; i += 256) s_w[6 * 256 + i] = loc_w[i];
    if (tid < 6)       s_b[tid] = score_b[tid];
    else if (tid < 18) s_b[tid] = loc_b[tid - 6];
    __syncthreads();

    int warp = tid >> 5, lane = tid & 31;
    int P = blockIdx.x * 8 + warp;
    if (P >= 26250) return;
    int n = P / 13125;
    int p = P % 13125;
    int aoff, hbase, ploc;
    if (p < 10000)      { ploc = p;         aoff = 0;     hbase = n * 2560000 + ploc * 256; }
    else if (p < 12500) { ploc = p - 10000; aoff = 30000; hbase = 5120000 + n * 640000 + ploc * 256; }
    else                { ploc = p - 12500; aoff = 37500; hbase = 6400000 + n * 160000 + ploc * 256; }

    const float4* hp = reinterpret_cast<const float4*>(&g_h[hbase]);
    float4 v0 = hp[lane];
    float4 v1 = hp[lane + 32];
    float hv[8] = {v0.x, v0.y, v0.z, v0.w, v1.x, v1.y, v1.z, v1.w};

    float res[18];
#pragma unroll
    for (int o = 0; o < 18; o++) {
        const float* wr = &s_w[o * 256];
        float4 wa = *reinterpret_cast<const float4*>(&wr[lane * 4]);
        float4 wb = *reinterpret_cast<const float4*>(&wr[128 + lane * 4]);
        float s = hv[0] * wa.x + hv[1] * wa.y + hv[2] * wa.z + hv[3] * wa.w +
                  hv[4] * wb.x + hv[5] * wb.y + hv[6] * wb.z + hv[7] * wb.w;
#pragma unroll
        for (int off = 16; off; off >>= 1) s += __shfl_xor_sync(0xffffffffu, s, off);
        res[o] = s + s_b[o];
    }

    if (lane == 0) {
        int aid0 = aoff + ploc * 3;
#pragma unroll
        for (int a = 0; a < 3; a++) {
            int aid = aid0 + a;
            float s0 = res[a * 2 + 0], s1 = res[a * 2 + 1];
            out[OFF_SCORES + (size_t)(n * A_TOTAL + aid) * 2 + 0] = s0;
            out[OFF_SCORES + (size_t)(n * A_TOTAL + aid) * 2 + 1] = s1;
            g_fg[n * A_TOTAL + aid] = 1.f / (1.f + expf(s0 - s1));
#pragma unroll
            for (int c = 0; c < 4; c++)
                out[OFF_LOCS + (size_t)(n * A_TOTAL + aid) * 4 + c] = res[6 + a * 4 + c];
        }
    }
}

// ---------------- fused propose + local sort (2048-segment) ----------------
__device__ __forceinline__ unsigned int flip_f(float f) {
    unsigned int b = __float_as_uint(f);
    return (b & 0x80000000u) ? ~b : (b | 0x80000000u);
}

__global__ __launch_bounds__(1024) void propose_sort(const float* __restrict__ anchors,
                                                     const float* __restrict__ out) {
    __shared__ unsigned long long sm[2048];
    int base = blockIdx.x * 2048;       // 64 blocks cover 2 x 65536
    int tid = threadIdx.x;

#pragma unroll
    for (int half = 0; half < 2; half++) {
        int e = tid + half * 1024;
        int t = base + e;
        int n = t / SORT_N, s = t % SORT_N;
        unsigned long long key = ~0ull;
        if (s < A_TOTAL) {
            float4 lc = *reinterpret_cast<const float4*>(out + OFF_LOCS + (size_t)(n * A_TOTAL + s) * 4);
            float4 an = *reinterpret_cast<const float4*>(anchors + (size_t)s * 4);
            float sh = an.z - an.x, sw = an.w - an.y;
            float cy = an.x + 0.5f * sh, cx = an.y + 0.5f * sw;
            float ncy = lc.x * sh + cy, ncx = lc.y * sw + cx;
            float nh = expf(lc.z) * sh, nw = expf(lc.w) * sw;
            float y1 = fminf(fmaxf(ncy - 0.5f * nh, 0.f), 800.f);
            float x1 = fminf(fmaxf(ncx - 0.5f * nw, 0.f), 800.f);
            float y2 = fminf(fmaxf(ncy + 0.5f * nh, 0.f), 800.f);
            float x2 = fminf(fmaxf(ncx + 0.5f * nw, 0.f), 800.f);
            *reinterpret_cast<float4*>(&g_roi[(size_t)(n * A_TOTAL + s) * 4]) =
                make_float4(y1, x1, y2, x2);
            bool valid = ((y2 - y1) >= 16.f) && ((x2 - x1) >= 16.f);
            float sc = valid ? g_fg[n * A_TOTAL + s] : -INFINITY;
            unsigned int u = flip_f(sc);
            key = ((unsigned long long)(~u) << 32) | (unsigned int)s;
        }
        sm[e] = key;
    }
    __syncthreads();

    for (int k = 2; k <= 2048; k <<= 1) {
        for (int j = k >> 1; j > 0; j >>= 1) {
            int i1 = ((tid / j) * 2 * j) + (tid % j);
            int i2 = i1 + j;
            bool dir = ((i1 & k) == 0);
            unsigned long long a = sm[i1], b = sm[i2];
            if (dir ? (a > b) : (a < b)) { sm[i1] = b; sm[i2] = a; }
            __syncthreads();
        }
    }
    g_keys[base + tid] = sm[tid];
    g_keys[base + tid + 1024] = sm[tid + 1024];
}

// ---------------- tournament merge-reduce ----------------
__global__ __launch_bounds__(1024) void merge_reduce(const unsigned long long* __restrict__ in,
                                                     unsigned long long* __restrict__ outb,
                                                     int runs_out_per_img) {
    __shared__ unsigned long long sm[2048];
    int img = blockIdx.x / runs_out_per_img;
    int r   = blockIdx.x % runs_out_per_img;
    const unsigned long long* A = in + (size_t)img * SORT_N + (size_t)(2 * r) * 2048;
    const unsigned long long* B = A + 2048;
    int tid = threadIdx.x;
    {
        unsigned long long a0 = A[tid],        b0 = B[2047 - tid];
        unsigned long long a1 = A[tid + 1024], b1 = B[1023 - tid];
        sm[tid]        = a0 < b0 ? a0 : b0;
        sm[tid + 1024] = a1 < b1 ? a1 : b1;
    }
    __syncthreads();
    for (int j = 1024; j > 0; j >>= 1) {
        int i1 = ((tid / j) * 2 * j) + (tid % j);
        int i2 = i1 + j;
        unsigned long long a = sm[i1], b = sm[i2];
        if (a > b) { sm[i1] = b; sm[i2] = a; }
        __syncthreads();
    }
    unsigned long long* O = outb + (size_t)img * SORT_N + (size_t)r * 2048;
    O[tid] = sm[tid];
    O[tid + 1024] = sm[tid + 1024];
}

// ---------------- gather top-2000 boxes ----------------
__global__ void gather_topk() {
    int t = blockIdx.x * 256 + threadIdx.x;
    if (t >= N_IMG * PRE) return;
    int n = t / PRE, r = t % PRE;
    unsigned long long key = g_keys2[(size_t)n * SORT_N + r];
    unsigned int hi = (unsigned int)(key >> 32);
    int valid = hi < 0xFF800000u;
    unsigned int idx = (unsigned int)key;
    float4 bx = make_float4(0.f, 0.f, 0.f, 0.f);
    if (idx < A_TOTAL)
        bx = *reinterpret_cast<const float4*>(&g_roi[(size_t)(n * A_TOTAL + idx) * 4]);
    *reinterpret_cast<float4*>(&g_boxes[(size_t)t * 4]) = bx;
    g_valid[t] = valid;
}

// ---------------- NMS suppression bitmask ----------------
__global__ void nms_mask() {
    int t = blockIdx.x * 256 + threadIdx.x;
    int n = blockIdx.y;
    if (t >= PRE * 32) return;
    int i = t >> 5, w = t & 31;
    const float4 bi = *reinterpret_cast<const float4*>(&g_boxes[(size_t)(n * PRE + i) * 4]);
    float area_i = (bi.z - bi.x) * (bi.w - bi.y);
    unsigned long long m = 0ull;
    int j0 = w * 64;
    for (int b = 0; b < 64; b++) {
        int j = j0 + b;
        if (j <= i || j >= PRE) continue;
        float4 bj = *reinterpret_cast<const float4*>(&g_boxes[(size_t)(n * PRE + j) * 4]);
        float ty = fmaxf(bi.x, bj.x), txx = fmaxf(bi.y, bj.y);
        float by = fminf(bi.z, bj.z), bxx = fminf(bi.w, bj.w);
        float hh = fmaxf(by - ty, 0.f), ww = fmaxf(bxx - txx, 0.f);
        float inter = hh * ww;
        float area_j = (bj.z - bj.x) * (bj.w - bj.y);
        float iou = inter / (area_i + area_j - inter + 1e-12f);
        if (iou > 0.7f) m |= (1ull << b);
    }
    g_mask[((size_t)n * PRE + i) * 32 + w] = m;
}

// ---------------- greedy NMS reduce (word-wise) + parallel emit ----------------
__global__ void nms_finalize(float* __restrict__ out) {
    int n = blockIdx.x;
    int tid = threadIdx.x;
    __shared__ unsigned long long alive_sh[32];
    __shared__ unsigned long long colm[64];
    __shared__ int base_sh[32];

    for (int i = tid; i < POST * 4; i += 256) out[OFF_ROIS + (size_t)n * POST * 4 + i] = 0.f;
    for (int i = tid; i < POST; i += 256)     out[OFF_RIDX + (size_t)n * POST + i] = (float)n;
    __syncthreads();

    if (tid < 32) {
        int lane = tid;
        unsigned long long sup = 0ull;
        for (int b = 0; b < 64; b++) {
            int i = lane * 64 + b;
            if (i >= PRE || !g_valid[n * PRE + i]) sup |= (1ull << b);
        }
        const unsigned long long* mrow = &g_mask[(size_t)n * PRE * 32];

        for (int w = 0; w < 32; w++) {
            int i0 = w * 64 + lane;
            int i1 = i0 + 32;
            colm[lane]      = (i0 < PRE) ? mrow[(size_t)i0 * 32 + w] : 0ull;
            colm[lane + 32] = (i1 < PRE) ? mrow[(size_t)i1 * 32 + w] : 0ull;
            __syncwarp();
            unsigned long long alivew = 0ull;
            if (lane == w) {
                unsigned long long supw = sup;
                for (int b = 0; b < 64; b++) {
                    if (!((supw >> b) & 1ull)) {
                        alivew |= (1ull << b);
                        supw |= colm[b];
                    }
                }
            }
            alivew = __shfl_sync(0xffffffffu, alivew, w);
            if (lane == w) alive_sh[w] = alivew;
            unsigned long long am = alivew, acc = 0ull;
            while (am) {
                int bb = __ffsll((long long)am) - 1;
                am &= am - 1;
                acc |= mrow[(size_t)(w * 64 + bb) * 32 + lane];
            }
            sup |= acc;
            __syncwarp();
        }

        int pc = __popcll(alive_sh[lane]);
        int xsum = pc;
        for (int off = 1; off < 32; off <<= 1) {
            int y = __shfl_up_sync(0xffffffffu, xsum, off);
            if (lane >= off) xsum += y;
        }
        base_sh[lane] = xsum - pc;
    }
    __syncthreads();

    for (int i = tid; i < PRE; i += 256) {
        int w = i >> 6, b = i & 63;
        unsigned long long aw = alive_sh[w];
        if ((aw >> b) & 1ull) {
            int rank = base_sh[w] + __popcll(aw & ((1ull << b) - 1ull));
            if (rank < POST) {
                float4 bx = *reinterpret_cast<const float4*>(&g_boxes[(size_t)(n * PRE + i) * 4]);
                float* dst = out + OFF_ROIS + (size_t)(n * POST + rank) * 4;
                dst[0] = bx.x; dst[1] = bx.y; dst[2] = bx.z; dst[3] = bx.w;
            }
        }
    }
}

// ---------------- launch ----------------
extern "C" void kernel_launch(void* const* d_in, const int* in_sizes, int n_in,
                              void* d_out, int out_size) {
    const float* feat0   = (const float*)d_in[0];
    const float* feat1   = (const float*)d_in[1];
    const float* feat2   = (const float*)d_in[2];
    const float* conv_w  = (const float*)d_in[3];
    const float* conv_b  = (const float*)d_in[4];
    const float* score_w = (const float*)d_in[5];
    const float* score_b = (const float*)d_in[6];
    const float* loc_w   = (const float*)d_in[7];
    const float* loc_b   = (const float*)d_in[8];
    const float* anchors = (const float*)d_in[9];
    float* out = (float*)d_out;

    unsigned long long *k1, *k2;
    cudaGetSymbolAddress((void**)&k1, g_keys);
    cudaGetSymbolAddress((void**)&k2, g_keys2);

    // Winograd conv pipeline (wino_output is the 4th launch = profiled)
    wino_weights<<<256, 256>>>(conv_w);
    wino_input<<<2208, 256>>>(feat0, feat1, feat2);
    wino_gemm<<<dim3(52, 2, 16), 256>>>();
    wino_output<<<T_TOTAL, 256>>>(conv_b);

    heads_kernel<<<3282, 256>>>(score_w, score_b, loc_w, loc_b, out);

    // fused propose + per-2048 local sort
    propose_sort<<<64, 1024>>>(anchors, out);

    merge_reduce<<<32, 1024>>>(k1, k2, 16);
    merge_reduce<<<16, 1024>>>(k2, k1, 8);
    merge_reduce<<< 8, 1024>>>(k1, k2, 4);
    merge_reduce<<< 4, 1024>>>(k2, k1, 2);
    merge_reduce<<< 2, 1024>>>(k1, k2, 1);

    gather_topk<<<16, 256>>>();
    nms_mask<<<dim3(250, 2), 256>>>();
    nms_finalize<<<2, 256>>>(out);

    cudaMemcpyAsync(out + OFF_ANCH, anchors, (size_t)A_TOTAL * 4 * sizeof(float),
                    cudaMemcpyDeviceToDevice, 0);
}